// round 1
// baseline (speedup 1.0000x reference)
#include <cuda_runtime.h>

// RGCN basis layer:
//   out = relu( scatter_dst( (w_comp[etype]*norm) . (h[src] @ W_b) ) + h@loop_w + bias )
// Plan:
//   K1: Z[M,640] = h[M,128] @ [W0|W1|W2|W3|loop_w]   (cols 0..511 -> Y scratch,
//       cols 512..639 -> out + bias, initializing the accumulator)
//   K2: per edge e: out[dst] += sum_b coeff[e,b] * Y[src, b*128..]
//   K3: out = relu(out)

#define HD 128
#define NB 4

// scratch: Y[N, 512] (N = 50000 fixed by the problem)
__device__ float g_Y[50000 * 512];

// ---------------------------------------------------------------------------
// K1: SGEMM 128x128 tile, K=128 in one shot, 256 threads, 8x8 microtile.
// ---------------------------------------------------------------------------
#define BM 128
#define BN 128
#define AS_STRIDE 132   // 132*4 = 528 bytes, 16B aligned rows, de-conflicted
#define SMEM_BYTES (2 * 128 * AS_STRIDE * 4)

__global__ __launch_bounds__(256) void gemm_k1(
    const float* __restrict__ h,
    const float* __restrict__ basis_w,
    const float* __restrict__ loop_w,
    const float* __restrict__ bias,
    float* __restrict__ out,
    int M)
{
    extern __shared__ float sm[];
    float* As = sm;                    // [128][AS_STRIDE]  (row = m, col = k)
    float* Bs = sm + 128 * AS_STRIDE;  // [128][AS_STRIDE]  (row = k, col = n)

    const int tid = threadIdx.x;
    const int m0  = blockIdx.x * BM;
    const int nt  = blockIdx.y;  // 0..3 = basis b, 4 = loop_w
    const float* Bsrc = (nt < NB) ? (basis_w + (size_t)nt * HD * HD) : loop_w;

    // --- global -> shared loads (float4, coalesced) ---
    {
        int c4 = tid & 31;   // float4 column (0..31) -> cols 4*c4..4*c4+3
        int r  = tid >> 5;   // row 0..7, step 8
        #pragma unroll
        for (int i = 0; i < 16; i++, r += 8) {
            float4 va = make_float4(0.f, 0.f, 0.f, 0.f);
            int gm = m0 + r;
            if (gm < M) va = *(const float4*)(h + (size_t)gm * HD + c4 * 4);
            *(float4*)(As + r * AS_STRIDE + c4 * 4) = va;

            float4 vb = *(const float4*)(Bsrc + (size_t)r * HD + c4 * 4);
            *(float4*)(Bs + r * AS_STRIDE + c4 * 4) = vb;
        }
    }
    __syncthreads();

    const int tm = tid >> 4;   // 0..15, rows tm*8 .. tm*8+7
    const int tn = tid & 15;   // 0..15, cols tn*8 .. tn*8+7

    float acc[8][8] = {};
    const float* ap = As + tm * 8 * AS_STRIDE;
    const float* bp = Bs + tn * 8;

    #pragma unroll 8
    for (int k = 0; k < 128; k++) {
        float a[8];
        #pragma unroll
        for (int i = 0; i < 8; i++) a[i] = ap[i * AS_STRIDE + k];
        float4 b0 = *(const float4*)(bp + k * AS_STRIDE);
        float4 b1 = *(const float4*)(bp + k * AS_STRIDE + 4);
        float b[8] = {b0.x, b0.y, b0.z, b0.w, b1.x, b1.y, b1.z, b1.w};
        #pragma unroll
        for (int i = 0; i < 8; i++)
            #pragma unroll
            for (int j = 0; j < 8; j++)
                acc[i][j] += a[i] * b[j];
    }

    // --- epilogue ---
    if (nt < NB) {
        // Y[gm*512 + nt*128 + (tn*8 + j)]
        #pragma unroll
        for (int i = 0; i < 8; i++) {
            int gm = m0 + tm * 8 + i;
            if (gm < M) {
                float* yp = g_Y + (size_t)gm * 512 + nt * HD + tn * 8;
                *(float4*)(yp)     = make_float4(acc[i][0], acc[i][1], acc[i][2], acc[i][3]);
                *(float4*)(yp + 4) = make_float4(acc[i][4], acc[i][5], acc[i][6], acc[i][7]);
            }
        }
    } else {
        float4 bi0 = *(const float4*)(bias + tn * 8);
        float4 bi1 = *(const float4*)(bias + tn * 8 + 4);
        #pragma unroll
        for (int i = 0; i < 8; i++) {
            int gm = m0 + tm * 8 + i;
            if (gm < M) {
                float* op = out + (size_t)gm * HD + tn * 8;
                *(float4*)(op)     = make_float4(acc[i][0] + bi0.x, acc[i][1] + bi0.y,
                                                 acc[i][2] + bi0.z, acc[i][3] + bi0.w);
                *(float4*)(op + 4) = make_float4(acc[i][4] + bi1.x, acc[i][5] + bi1.y,
                                                 acc[i][6] + bi1.z, acc[i][7] + bi1.w);
            }
        }
    }
}

// ---------------------------------------------------------------------------
// K2: one warp per edge. Warp reads the full 2KB Y row of src (coalesced),
// combines the 4 basis blocks with per-edge coefficients, vector-red into out.
// ---------------------------------------------------------------------------
__global__ __launch_bounds__(256) void edge_scatter(
    const float* __restrict__ w_comp,
    const float* __restrict__ norm,
    const int* __restrict__ src,
    const int* __restrict__ dst,
    const int* __restrict__ etype,
    float* __restrict__ out,
    int E)
{
    int warp = (blockIdx.x * blockDim.x + threadIdx.x) >> 5;
    int lane = threadIdx.x & 31;
    if (warp >= E) return;

    int s = src[warp];
    int d = dst[warp];
    int t = etype[warp];
    float nm = norm[warp];

    float c0 = w_comp[t * NB + 0] * nm;
    float c1 = w_comp[t * NB + 1] * nm;
    float c2 = w_comp[t * NB + 2] * nm;
    float c3 = w_comp[t * NB + 3] * nm;

    const float4* yr = (const float4*)(g_Y) + (size_t)s * 128;  // 512 floats = 128 float4
    float4 v0 = yr[lane];
    float4 v1 = yr[32 + lane];
    float4 v2 = yr[64 + lane];
    float4 v3 = yr[96 + lane];

    float ax = c0 * v0.x + c1 * v1.x + c2 * v2.x + c3 * v3.x;
    float ay = c0 * v0.y + c1 * v1.y + c2 * v2.y + c3 * v3.y;
    float az = c0 * v0.z + c1 * v1.z + c2 * v2.z + c3 * v3.z;
    float aw = c0 * v0.w + c1 * v1.w + c2 * v2.w + c3 * v3.w;

    float* op = out + (size_t)d * HD + lane * 4;
    asm volatile("red.global.add.v4.f32 [%0], {%1, %2, %3, %4};"
                 :: "l"(op), "f"(ax), "f"(ay), "f"(az), "f"(aw)
                 : "memory");
}

// ---------------------------------------------------------------------------
// K3: in-place relu
// ---------------------------------------------------------------------------
__global__ __launch_bounds__(256) void relu_k(float* __restrict__ out, int n4)
{
    int i = blockIdx.x * blockDim.x + threadIdx.x;
    if (i < n4) {
        float4 v = ((float4*)out)[i];
        v.x = fmaxf(v.x, 0.f);
        v.y = fmaxf(v.y, 0.f);
        v.z = fmaxf(v.z, 0.f);
        v.w = fmaxf(v.w, 0.f);
        ((float4*)out)[i] = v;
    }
}

extern "C" void kernel_launch(void* const* d_in, const int* in_sizes, int n_in,
                              void* d_out, int out_size)
{
    const float* h       = (const float*)d_in[0];
    const float* norm    = (const float*)d_in[1];
    const float* basis_w = (const float*)d_in[2];
    const float* w_comp  = (const float*)d_in[3];
    const float* loop_w  = (const float*)d_in[4];
    const float* bias    = (const float*)d_in[5];
    const int*   src     = (const int*)d_in[6];
    const int*   dst     = (const int*)d_in[7];
    const int*   etype   = (const int*)d_in[8];
    float* out = (float*)d_out;

    int M = in_sizes[0] / HD;   // 50000
    int E = in_sizes[6];        // 800000

    cudaFuncSetAttribute(gemm_k1, cudaFuncAttributeMaxDynamicSharedMemorySize, SMEM_BYTES);

    dim3 g1((M + BM - 1) / BM, NB + 1);
    gemm_k1<<<g1, 256, SMEM_BYTES>>>(h, basis_w, loop_w, bias, out, M);

    int blocks2 = (E + 7) / 8;  // 8 warps/block, 1 edge/warp
    edge_scatter<<<blocks2, 256>>>(w_comp, norm, src, dst, etype, out, E);

    int n4 = M * HD / 4;
    relu_k<<<(n4 + 255) / 256, 256>>>(out, n4);
}

// round 2
// speedup vs baseline: 1.1591x; 1.1591x over previous
#include <cuda_runtime.h>
#include <cuda_fp16.h>

// RGCN basis layer:
//   out = relu( scatter_dst( (w_comp[etype]*norm) . (h[src] @ W_b) ) + h@loop_w + bias )
// Plan:
//   K0: hT[128, MP] = transpose(h)                     (k-major A for vectorized LDS)
//   K1: Z[M,640] = h[M,128] @ [W0|W1|W2|W3|loop_w]     (cols 0..511 -> Y (fp16) scratch,
//       cols 512..639 -> out + bias, initializing the accumulator)
//   K2: per edge e: out[dst] += sum_b coeff[e,b] * Y[src, b*128..]   (half gather, v4 red)
//   K3: out = relu(out)

#define HD 128
#define NB 4
#define NNODES 50000
#define MP 50048            // padded M (multiple of 128)

__device__ __half g_Yh[(size_t)NNODES * 512];   // fp16 Y scratch, 51.2 MB
__device__ float  g_hT[(size_t)HD * MP];        // transposed h, 25.6 MB

// ---------------------------------------------------------------------------
// K0: transpose h [M,128] -> hT [128, MP], zero-padded for m >= M
// ---------------------------------------------------------------------------
__global__ __launch_bounds__(256) void transpose_h(const float* __restrict__ h, int M)
{
    __shared__ float t[32][33];
    int mBase = blockIdx.x * 32;
    int kBase = blockIdx.y * 32;
    int lx = threadIdx.x;        // 0..31
    int ly = threadIdx.y;        // 0..7
    #pragma unroll
    for (int j = 0; j < 32; j += 8) {
        int m = mBase + ly + j;
        t[ly + j][lx] = (m < M) ? h[(size_t)m * HD + kBase + lx] : 0.f;
    }
    __syncthreads();
    #pragma unroll
    for (int j = 0; j < 32; j += 8) {
        int k = kBase + ly + j;
        g_hT[(size_t)k * MP + mBase + lx] = t[lx][ly + j];
    }
}

// ---------------------------------------------------------------------------
// K1: SGEMM 128x128 tile, K=128, 256 threads, 8x8 microtile.
// A fragment from k-major hT => all smem loads are conflict-free LDS.128.
// ---------------------------------------------------------------------------
#define BM 128
#define SM_STRIDE 132
#define SMEM_BYTES (2 * 128 * SM_STRIDE * 4)

__global__ __launch_bounds__(256) void gemm_k1(
    const float* __restrict__ basis_w,
    const float* __restrict__ loop_w,
    const float* __restrict__ bias,
    float* __restrict__ out,
    int M)
{
    extern __shared__ float sm[];
    float* As = sm;                      // [k=128][m=128+pad]
    float* Bs = sm + 128 * SM_STRIDE;    // [k=128][n=128+pad]

    const int tid = threadIdx.x;
    const int m0  = blockIdx.x * BM;
    const int nt  = blockIdx.y;  // 0..3 = basis b, 4 = loop_w
    const float* Bsrc = (nt < NB) ? (basis_w + (size_t)nt * HD * HD) : loop_w;

    // --- global -> shared (both operands k-major, coalesced float4, conflict-free STS) ---
    {
        int c4 = tid & 31;   // float4 index within a row (cols 4*c4..4*c4+3)
        int r  = tid >> 5;   // k row, step 8
        #pragma unroll
        for (int i = 0; i < 16; i++, r += 8) {
            float4 va = *(const float4*)(g_hT + (size_t)r * MP + m0 + c4 * 4);
            *(float4*)(As + r * SM_STRIDE + c4 * 4) = va;
            float4 vb = *(const float4*)(Bsrc + (size_t)r * HD + c4 * 4);
            *(float4*)(Bs + r * SM_STRIDE + c4 * 4) = vb;
        }
    }
    __syncthreads();

    const int tm = tid >> 4;   // 0..15 -> rows tm*8..tm*8+7
    const int tn = tid & 15;   // 0..15 -> cols tn*8..tn*8+7

    float acc[8][8] = {};
    const float* ap = As + tm * 8;
    const float* bp = Bs + tn * 8;

    #pragma unroll 8
    for (int k = 0; k < 128; k++) {
        float4 a0 = *(const float4*)(ap + k * SM_STRIDE);
        float4 a1 = *(const float4*)(ap + k * SM_STRIDE + 4);
        float4 b0 = *(const float4*)(bp + k * SM_STRIDE);
        float4 b1 = *(const float4*)(bp + k * SM_STRIDE + 4);
        float a[8] = {a0.x, a0.y, a0.z, a0.w, a1.x, a1.y, a1.z, a1.w};
        float b[8] = {b0.x, b0.y, b0.z, b0.w, b1.x, b1.y, b1.z, b1.w};
        #pragma unroll
        for (int i = 0; i < 8; i++)
            #pragma unroll
            for (int j = 0; j < 8; j++)
                acc[i][j] += a[i] * b[j];
    }

    // --- epilogue ---
    if (nt < NB) {
        // Y (fp16): g_Yh[gm*512 + nt*128 + tn*8 .. +7]
        #pragma unroll
        for (int i = 0; i < 8; i++) {
            int gm = m0 + tm * 8 + i;
            if (gm < M) {
                __half2 p0 = __floats2half2_rn(acc[i][0], acc[i][1]);
                __half2 p1 = __floats2half2_rn(acc[i][2], acc[i][3]);
                __half2 p2 = __floats2half2_rn(acc[i][4], acc[i][5]);
                __half2 p3 = __floats2half2_rn(acc[i][6], acc[i][7]);
                __half2* yp = (__half2*)(g_Yh + (size_t)gm * 512 + nt * HD + tn * 8);
                yp[0] = p0; yp[1] = p1; yp[2] = p2; yp[3] = p3;
            }
        }
    } else {
        float4 bi0 = *(const float4*)(bias + tn * 8);
        float4 bi1 = *(const float4*)(bias + tn * 8 + 4);
        #pragma unroll
        for (int i = 0; i < 8; i++) {
            int gm = m0 + tm * 8 + i;
            if (gm < M) {
                float* op = out + (size_t)gm * HD + tn * 8;
                *(float4*)(op)     = make_float4(acc[i][0] + bi0.x, acc[i][1] + bi0.y,
                                                 acc[i][2] + bi0.z, acc[i][3] + bi0.w);
                *(float4*)(op + 4) = make_float4(acc[i][4] + bi1.x, acc[i][5] + bi1.y,
                                                 acc[i][6] + bi1.z, acc[i][7] + bi1.w);
            }
        }
    }
}

// ---------------------------------------------------------------------------
// K2: one warp per edge. Lane l covers out cols 4l..4l+3; gathers 4x half4
// (8B coalesced) from Y's 4 basis blocks, combines, v4 reduction into out.
// ---------------------------------------------------------------------------
struct alignas(8) Half4 { __half2 lo, hi; };

__global__ __launch_bounds__(256) void edge_scatter(
    const float* __restrict__ w_comp,
    const float* __restrict__ norm,
    const int* __restrict__ src,
    const int* __restrict__ dst,
    const int* __restrict__ etype,
    float* __restrict__ out,
    int E)
{
    int warp = (blockIdx.x * blockDim.x + threadIdx.x) >> 5;
    int lane = threadIdx.x & 31;
    if (warp >= E) return;

    int s = src[warp];
    int d = dst[warp];
    int t = etype[warp];
    float nm = norm[warp];

    float c0 = w_comp[t * NB + 0] * nm;
    float c1 = w_comp[t * NB + 1] * nm;
    float c2 = w_comp[t * NB + 2] * nm;
    float c3 = w_comp[t * NB + 3] * nm;

    const __half* Y = g_Yh + (size_t)s * 512;
    Half4 v0 = *(const Half4*)(Y + 0 * HD + lane * 4);
    Half4 v1 = *(const Half4*)(Y + 1 * HD + lane * 4);
    Half4 v2 = *(const Half4*)(Y + 2 * HD + lane * 4);
    Half4 v3 = *(const Half4*)(Y + 3 * HD + lane * 4);

    float2 l0 = __half22float2(v0.lo), h0 = __half22float2(v0.hi);
    float2 l1 = __half22float2(v1.lo), h1 = __half22float2(v1.hi);
    float2 l2 = __half22float2(v2.lo), h2 = __half22float2(v2.hi);
    float2 l3 = __half22float2(v3.lo), h3 = __half22float2(v3.hi);

    float ax = c0 * l0.x + c1 * l1.x + c2 * l2.x + c3 * l3.x;
    float ay = c0 * l0.y + c1 * l1.y + c2 * l2.y + c3 * l3.y;
    float az = c0 * h0.x + c1 * h1.x + c2 * h2.x + c3 * h3.x;
    float aw = c0 * h0.y + c1 * h1.y + c2 * h2.y + c3 * h3.y;

    float* op = out + (size_t)d * HD + lane * 4;
    asm volatile("red.global.add.v4.f32 [%0], {%1, %2, %3, %4};"
                 :: "l"(op), "f"(ax), "f"(ay), "f"(az), "f"(aw)
                 : "memory");
}

// ---------------------------------------------------------------------------
// K3: in-place relu
// ---------------------------------------------------------------------------
__global__ __launch_bounds__(256) void relu_k(float* __restrict__ out, int n4)
{
    int i = blockIdx.x * blockDim.x + threadIdx.x;
    if (i < n4) {
        float4 v = ((float4*)out)[i];
        v.x = fmaxf(v.x, 0.f);
        v.y = fmaxf(v.y, 0.f);
        v.z = fmaxf(v.z, 0.f);
        v.w = fmaxf(v.w, 0.f);
        ((float4*)out)[i] = v;
    }
}

extern "C" void kernel_launch(void* const* d_in, const int* in_sizes, int n_in,
                              void* d_out, int out_size)
{
    const float* h       = (const float*)d_in[0];
    const float* norm    = (const float*)d_in[1];
    const float* basis_w = (const float*)d_in[2];
    const float* w_comp  = (const float*)d_in[3];
    const float* loop_w  = (const float*)d_in[4];
    const float* bias    = (const float*)d_in[5];
    const int*   src     = (const int*)d_in[6];
    const int*   dst     = (const int*)d_in[7];
    const int*   etype   = (const int*)d_in[8];
    float* out = (float*)d_out;

    int M = in_sizes[0] / HD;   // 50000
    int E = in_sizes[6];        // 800000

    cudaFuncSetAttribute(gemm_k1, cudaFuncAttributeMaxDynamicSharedMemorySize, SMEM_BYTES);

    dim3 g0(MP / 32, HD / 32);
    transpose_h<<<g0, dim3(32, 8)>>>(h, M);

    dim3 g1((M + BM - 1) / BM, NB + 1);
    gemm_k1<<<g1, 256, SMEM_BYTES>>>(basis_w, loop_w, bias, out, M);

    int blocks2 = (E + 7) / 8;  // 8 warps/block, 1 edge/warp
    edge_scatter<<<blocks2, 256>>>(w_comp, norm, src, dst, etype, out, E);

    int n4 = M * HD / 4;
    relu_k<<<(n4 + 255) / 256, 256>>>(out, n4);
}

// round 4
// speedup vs baseline: 1.6443x; 1.4186x over previous
#include <cuda_runtime.h>
#include <cuda_fp16.h>
#include <cstdint>

// RGCN basis layer:
//   out = relu( scatter_dst( (w_comp[etype]*norm) . (h[src] @ W_b) ) + h@loop_w + bias )
// Plan:
//   K0: WT[640][128] = tf32-rounded n-major stack of [W0|W1|W2|W3|loop_w]
//   K1: tf32 tensor-core GEMM  Z[M,640] = h[M,128] @ Wstack
//       cols 0..511 -> Y (fp16) scratch; cols 512..639 -> out + bias
//   K2: per edge e: out[dst] += sum_b coeff[e,b] * Y[src, b*128..]  (half gather, v4 red)
//   K3: out = relu(out)

#define HD 128
#define NB 4
#define NNODES 50000
#define NCOLS 640
#define SMS 132     // smem row stride in floats (528B, 16B aligned, conflict-free)

__device__ __half g_Yh[(size_t)NNODES * 512];   // fp16 Y scratch, 51.2 MB
__device__ float  g_WT[NCOLS * HD];             // n-major weight stack, tf32-rounded

static __device__ __forceinline__ uint32_t smem_u32(const void* p) {
    uint32_t a;
    asm("{ .reg .u64 t; cvta.to.shared.u64 t, %1; cvt.u32.u64 %0, t; }" : "=r"(a) : "l"(p));
    return a;
}

// ---------------------------------------------------------------------------
// K0: WT[n][k] = round_tf32( Wstack[k][n] )
// ---------------------------------------------------------------------------
__global__ __launch_bounds__(256) void wt_transpose(
    const float* __restrict__ basis_w, const float* __restrict__ loop_w)
{
    int idx = blockIdx.x * blockDim.x + threadIdx.x;
    if (idx >= NCOLS * HD) return;
    int n = idx >> 7;          // 0..639
    int k = idx & 127;
    float v;
    if (n < NB * HD) {
        int b = n >> 7, np = n & 127;
        v = basis_w[(size_t)b * HD * HD + (size_t)k * HD + np];
    } else {
        v = loop_w[(size_t)k * HD + (n - NB * HD)];
    }
    uint32_t t;
    asm("cvt.rna.tf32.f32 %0, %1;" : "=r"(t) : "f"(v));
    ((uint32_t*)g_WT)[idx] = t;
}

// ---------------------------------------------------------------------------
// K1: tf32 mma.sync GEMM. Block tile 128(m) x 64(n), K=128 in one smem load.
// 8 warps = 4(m) x 2(n); warp tile 32x32; mma m16n8k8; ldmatrix fragments.
// ---------------------------------------------------------------------------
#define SMEM_BYTES ((128 + 64) * SMS * 4)

__global__ __launch_bounds__(256) void gemm_tc(
    const float* __restrict__ h,
    const float* __restrict__ bias,
    float* __restrict__ out,
    int M)
{
    extern __shared__ float smf[];
    float* As = smf;              // [m=128][k=SMS]
    float* Bs = smf + 128 * SMS;  // [n=64][k=SMS]

    const int tid = threadIdx.x;
    const int m0  = blockIdx.x * 128;
    const int n0  = blockIdx.y * 64;

    // ---- fill smem (A rounded to tf32 here; B pre-rounded in g_WT) ----
    {
        int c4 = tid & 31;       // float4 index along k
        int r  = tid >> 5;       // row, step 8
        #pragma unroll
        for (int i = 0; i < 16; i++, r += 8) {
            int gm = m0 + r;
            float4 v = (gm < M) ? *(const float4*)(h + (size_t)gm * HD + c4 * 4)
                                : make_float4(0.f, 0.f, 0.f, 0.f);
            uint32_t t0, t1, t2, t3;
            asm("cvt.rna.tf32.f32 %0, %1;" : "=r"(t0) : "f"(v.x));
            asm("cvt.rna.tf32.f32 %0, %1;" : "=r"(t1) : "f"(v.y));
            asm("cvt.rna.tf32.f32 %0, %1;" : "=r"(t2) : "f"(v.z));
            asm("cvt.rna.tf32.f32 %0, %1;" : "=r"(t3) : "f"(v.w));
            uint4 u = make_uint4(t0, t1, t2, t3);
            *(uint4*)(As + r * SMS + c4 * 4) = u;
        }
        r = tid >> 5;
        #pragma unroll
        for (int i = 0; i < 8; i++, r += 8) {
            float4 v = *(const float4*)(g_WT + (size_t)(n0 + r) * HD + c4 * 4);
            *(float4*)(Bs + r * SMS + c4 * 4) = v;
        }
    }
    __syncthreads();

    const int lane = tid & 31;
    const int w    = tid >> 5;
    const int wm   = w & 3;     // m quarter (32 rows)
    const int wn   = w >> 2;    // n half   (32 cols)

    // ldmatrix per-lane address pattern (same for A and B):
    //  lanes 0-7: rows r, k+0 | 8-15: rows r+8, k+0 | 16-23: rows r, k+4 | 24-31: rows r+8, k+4
    const int r8     = lane & 7;
    const int sel    = lane >> 3;
    const int rowoff = r8 + ((sel & 1) << 3);
    const int koff   = (sel & 2) ? 4 : 0;

    uint32_t aAddr[2], bAddr[2];
    #pragma unroll
    for (int mt = 0; mt < 2; mt++)
        aAddr[mt] = smem_u32(As + (wm * 32 + mt * 16 + rowoff) * SMS + koff);
    #pragma unroll
    for (int p = 0; p < 2; p++)
        bAddr[p] = smem_u32(Bs + (wn * 32 + p * 16 + rowoff) * SMS + koff);

    float acc[2][4][4];
    #pragma unroll
    for (int mt = 0; mt < 2; mt++)
        #pragma unroll
        for (int nt = 0; nt < 4; nt++)
            #pragma unroll
            for (int q = 0; q < 4; q++) acc[mt][nt][q] = 0.f;

    #pragma unroll
    for (int k0 = 0; k0 < 128; k0 += 8) {
        uint32_t a[2][4], b[2][4];
        #pragma unroll
        for (int mt = 0; mt < 2; mt++)
            asm volatile("ldmatrix.sync.aligned.m8n8.x4.shared.b16 {%0,%1,%2,%3}, [%4];"
                         : "=r"(a[mt][0]), "=r"(a[mt][1]), "=r"(a[mt][2]), "=r"(a[mt][3])
                         : "r"(aAddr[mt] + k0 * 4));
        #pragma unroll
        for (int p = 0; p < 2; p++)
            asm volatile("ldmatrix.sync.aligned.m8n8.x4.shared.b16 {%0,%1,%2,%3}, [%4];"
                         : "=r"(b[p][0]), "=r"(b[p][1]), "=r"(b[p][2]), "=r"(b[p][3])
                         : "r"(bAddr[p] + k0 * 4));
        // b[p]: r0=b0(ntile 2p), r1=b0(ntile 2p+1), r2=b1(ntile 2p), r3=b1(ntile 2p+1)
        #pragma unroll
        for (int mt = 0; mt < 2; mt++)
            #pragma unroll
            for (int nt = 0; nt < 4; nt++) {
                int p = nt >> 1, q = nt & 1;
                asm volatile(
                    "mma.sync.aligned.m16n8k8.row.col.f32.tf32.tf32.f32 "
                    "{%0,%1,%2,%3}, {%4,%5,%6,%7}, {%8,%9}, {%0,%1,%2,%3};"
                    : "+f"(acc[mt][nt][0]), "+f"(acc[mt][nt][1]),
                      "+f"(acc[mt][nt][2]), "+f"(acc[mt][nt][3])
                    : "r"(a[mt][0]), "r"(a[mt][1]), "r"(a[mt][2]), "r"(a[mt][3]),
                      "r"(b[p][q]), "r"(b[p][q + 2]));
            }
    }

    // ---- epilogue ----
    // mma D layout: c0:(row,col) c1:(row,col+1) c2:(row+8,col) c3:(row+8,col+1)
    // row = lane/4, col = 2*(lane%4)
    const int rbase = lane >> 2;
    const int col2  = (lane & 3) * 2;
    const bool isY  = (blockIdx.y < 8);

    #pragma unroll
    for (int mt = 0; mt < 2; mt++) {
        #pragma unroll
        for (int hh = 0; hh < 2; hh++) {
            int gm = m0 + wm * 32 + mt * 16 + rbase + hh * 8;
            if (gm >= M) continue;
            #pragma unroll
            for (int nt = 0; nt < 4; nt++) {
                int gn = n0 + wn * 32 + nt * 8 + col2;
                float c0 = acc[mt][nt][hh * 2];
                float c1 = acc[mt][nt][hh * 2 + 1];
                if (isY) {
                    // gn in [0,512): basis b = gn>>7, col = gn&127
                    *(__half2*)(g_Yh + (size_t)gm * 512 + gn) = __floats2half2_rn(c0, c1);
                } else {
                    int co = gn - 512;
                    float2 o;
                    o.x = c0 + bias[co];
                    o.y = c1 + bias[co + 1];
                    *(float2*)(out + (size_t)gm * HD + co) = o;
                }
            }
        }
    }
}

// ---------------------------------------------------------------------------
// K2: one warp per edge; gather full 1KB fp16 Y row of src; v4 reduction.
// ---------------------------------------------------------------------------
struct alignas(8) Half4 { __half2 lo, hi; };

__global__ __launch_bounds__(256) void edge_scatter(
    const float* __restrict__ w_comp,
    const float* __restrict__ norm,
    const int* __restrict__ src,
    const int* __restrict__ dst,
    const int* __restrict__ etype,
    float* __restrict__ out,
    int E)
{
    int warp = (blockIdx.x * blockDim.x + threadIdx.x) >> 5;
    int lane = threadIdx.x & 31;
    if (warp >= E) return;

    int s = src[warp];
    int d = dst[warp];
    int t = etype[warp];
    float nm = norm[warp];

    float c0 = w_comp[t * NB + 0] * nm;
    float c1 = w_comp[t * NB + 1] * nm;
    float c2 = w_comp[t * NB + 2] * nm;
    float c3 = w_comp[t * NB + 3] * nm;

    const __half* Y = g_Yh + (size_t)s * 512;
    Half4 v0 = *(const Half4*)(Y + 0 * HD + lane * 4);
    Half4 v1 = *(const Half4*)(Y + 1 * HD + lane * 4);
    Half4 v2 = *(const Half4*)(Y + 2 * HD + lane * 4);
    Half4 v3 = *(const Half4*)(Y + 3 * HD + lane * 4);

    float2 l0 = __half22float2(v0.lo), h0 = __half22float2(v0.hi);
    float2 l1 = __half22float2(v1.lo), h1 = __half22float2(v1.hi);
    float2 l2 = __half22float2(v2.lo), h2 = __half22float2(v2.hi);
    float2 l3 = __half22float2(v3.lo), h3 = __half22float2(v3.hi);

    float ax = c0 * l0.x + c1 * l1.x + c2 * l2.x + c3 * l3.x;
    float ay = c0 * l0.y + c1 * l1.y + c2 * l2.y + c3 * l3.y;
    float az = c0 * h0.x + c1 * h1.x + c2 * h2.x + c3 * h3.x;
    float aw = c0 * h0.y + c1 * h1.y + c2 * h2.y + c3 * h3.y;

    float* op = out + (size_t)d * HD + lane * 4;
    asm volatile("red.global.add.v4.f32 [%0], {%1, %2, %3, %4};"
                 :: "l"(op), "f"(ax), "f"(ay), "f"(az), "f"(aw)
                 : "memory");
}

// ---------------------------------------------------------------------------
// K3: in-place relu
// ---------------------------------------------------------------------------
__global__ __launch_bounds__(256) void relu_k(float* __restrict__ out, int n4)
{
    int i = blockIdx.x * blockDim.x + threadIdx.x;
    if (i < n4) {
        float4 v = ((float4*)out)[i];
        v.x = fmaxf(v.x, 0.f);
        v.y = fmaxf(v.y, 0.f);
        v.z = fmaxf(v.z, 0.f);
        v.w = fmaxf(v.w, 0.f);
        ((float4*)out)[i] = v;
    }
}

extern "C" void kernel_launch(void* const* d_in, const int* in_sizes, int n_in,
                              void* d_out, int out_size)
{
    const float* h       = (const float*)d_in[0];
    const float* norm    = (const float*)d_in[1];
    const float* basis_w = (const float*)d_in[2];
    const float* w_comp  = (const float*)d_in[3];
    const float* loop_w  = (const float*)d_in[4];
    const float* bias    = (const float*)d_in[5];
    const int*   src     = (const int*)d_in[6];
    const int*   dst     = (const int*)d_in[7];
    const int*   etype   = (const int*)d_in[8];
    float* out = (float*)d_out;

    int M = in_sizes[0] / HD;   // 50000
    int E = in_sizes[6];        // 800000

    cudaFuncSetAttribute(gemm_tc, cudaFuncAttributeMaxDynamicSharedMemorySize, SMEM_BYTES);

    wt_transpose<<<(NCOLS * HD + 255) / 256, 256>>>(basis_w, loop_w);

    dim3 g1((M + 127) / 128, NCOLS / 64);
    gemm_tc<<<g1, 256, SMEM_BYTES>>>(h, bias, out, M);

    int blocks2 = (E + 7) / 8;  // 8 warps/block, 1 edge/warp
    edge_scatter<<<blocks2, 256>>>(w_comp, norm, src, dst, etype, out, E);

    int n4 = M * HD / 4;
    relu_k<<<(n4 + 255) / 256, 256>>>(out, n4);
}

// round 5
// speedup vs baseline: 1.7958x; 1.0921x over previous
#include <cuda_runtime.h>
#include <cuda_fp16.h>
#include <cstdint>

// RGCN basis layer:
//   out = relu( scatter_dst( (w_comp[etype]*norm) . (h[src] @ W_b) ) + h@loop_w + bias )
// Plan:
//   K0: WT[640][128] = tf32-rounded n-major stack of [W0|W1|W2|W3|loop_w]
//   K1: tf32 tensor-core GEMM  Z[M,640] = h[M,128] @ Wstack
//       cols 0..511 -> Y (fp16) scratch; cols 512..639 -> out + bias  (accumulator init)
//   CSR build: counts -> exclusive scan -> bucket-scatter (src, c0..c3) per edge
//   K_acc: warp per dst node: acc = out[v]; for each edge: acc += sum_b c_b * Y[src,b*128..];
//          out[v] = relu(acc)    (no atomics, relu fused)

#define HD 128
#define NB 4
#define NNODES 50000
#define NEDGES 800000
#define NP 50176            // 196 * 256, padded node count
#define NBLK 196
#define NCOLS 640
#define SMS 132             // smem row stride in floats (528B, conflict-free)

__device__ __half g_Yh[(size_t)NNODES * 512];   // fp16 Y scratch, 51.2 MB
__device__ float  g_WT[NCOLS * HD];             // n-major weight stack, tf32-rounded

// CSR scratch
__device__ int    g_cnt[NP];
__device__ int    g_cur[NP];
__device__ int    g_off[NP];
__device__ int    g_bsum[NBLK];
__device__ int    g_bscan[NBLK];
__device__ int    g_esrc[NEDGES];
__device__ float4 g_ecoef[NEDGES];

static __device__ __forceinline__ uint32_t smem_u32(const void* p) {
    uint32_t a;
    asm("{ .reg .u64 t; cvta.to.shared.u64 t, %1; cvt.u32.u64 %0, t; }" : "=r"(a) : "l"(p));
    return a;
}

// ---------------------------------------------------------------------------
// K0: WT[n][k] = round_tf32( Wstack[k][n] )
// ---------------------------------------------------------------------------
__global__ __launch_bounds__(256) void wt_transpose(
    const float* __restrict__ basis_w, const float* __restrict__ loop_w)
{
    int idx = blockIdx.x * blockDim.x + threadIdx.x;
    if (idx >= NCOLS * HD) return;
    int n = idx >> 7;
    int k = idx & 127;
    float v;
    if (n < NB * HD) {
        int b = n >> 7, np = n & 127;
        v = basis_w[(size_t)b * HD * HD + (size_t)k * HD + np];
    } else {
        v = loop_w[(size_t)k * HD + (n - NB * HD)];
    }
    uint32_t t;
    asm("cvt.rna.tf32.f32 %0, %1;" : "=r"(t) : "f"(v));
    ((uint32_t*)g_WT)[idx] = t;
}

// ---------------------------------------------------------------------------
// K1: tf32 mma.sync GEMM. Block tile 128(m) x 64(n), K=128, 8 warps.
// ---------------------------------------------------------------------------
#define SMEM_BYTES ((128 + 64) * SMS * 4)

__global__ __launch_bounds__(256) void gemm_tc(
    const float* __restrict__ h,
    const float* __restrict__ bias,
    float* __restrict__ out,
    int M)
{
    extern __shared__ float smf[];
    float* As = smf;              // [m=128][k=SMS]
    float* Bs = smf + 128 * SMS;  // [n=64][k=SMS]

    const int tid = threadIdx.x;
    const int m0  = blockIdx.x * 128;
    const int n0  = blockIdx.y * 64;

    {
        int c4 = tid & 31;
        int r  = tid >> 5;
        #pragma unroll
        for (int i = 0; i < 16; i++, r += 8) {
            int gm = m0 + r;
            float4 v = (gm < M) ? *(const float4*)(h + (size_t)gm * HD + c4 * 4)
                                : make_float4(0.f, 0.f, 0.f, 0.f);
            uint32_t t0, t1, t2, t3;
            asm("cvt.rna.tf32.f32 %0, %1;" : "=r"(t0) : "f"(v.x));
            asm("cvt.rna.tf32.f32 %0, %1;" : "=r"(t1) : "f"(v.y));
            asm("cvt.rna.tf32.f32 %0, %1;" : "=r"(t2) : "f"(v.z));
            asm("cvt.rna.tf32.f32 %0, %1;" : "=r"(t3) : "f"(v.w));
            uint4 u = make_uint4(t0, t1, t2, t3);
            *(uint4*)(As + r * SMS + c4 * 4) = u;
        }
        r = tid >> 5;
        #pragma unroll
        for (int i = 0; i < 8; i++, r += 8) {
            float4 v = *(const float4*)(g_WT + (size_t)(n0 + r) * HD + c4 * 4);
            *(float4*)(Bs + r * SMS + c4 * 4) = v;
        }
    }
    __syncthreads();

    const int lane = tid & 31;
    const int w    = tid >> 5;
    const int wm   = w & 3;
    const int wn   = w >> 2;

    const int r8     = lane & 7;
    const int sel    = lane >> 3;
    const int rowoff = r8 + ((sel & 1) << 3);
    const int koff   = (sel & 2) ? 4 : 0;

    uint32_t aAddr[2], bAddr[2];
    #pragma unroll
    for (int mt = 0; mt < 2; mt++)
        aAddr[mt] = smem_u32(As + (wm * 32 + mt * 16 + rowoff) * SMS + koff);
    #pragma unroll
    for (int p = 0; p < 2; p++)
        bAddr[p] = smem_u32(Bs + (wn * 32 + p * 16 + rowoff) * SMS + koff);

    float acc[2][4][4];
    #pragma unroll
    for (int mt = 0; mt < 2; mt++)
        #pragma unroll
        for (int nt = 0; nt < 4; nt++)
            #pragma unroll
            for (int q = 0; q < 4; q++) acc[mt][nt][q] = 0.f;

    #pragma unroll
    for (int k0 = 0; k0 < 128; k0 += 8) {
        uint32_t a[2][4], b[2][4];
        #pragma unroll
        for (int mt = 0; mt < 2; mt++)
            asm volatile("ldmatrix.sync.aligned.m8n8.x4.shared.b16 {%0,%1,%2,%3}, [%4];"
                         : "=r"(a[mt][0]), "=r"(a[mt][1]), "=r"(a[mt][2]), "=r"(a[mt][3])
                         : "r"(aAddr[mt] + k0 * 4));
        #pragma unroll
        for (int p = 0; p < 2; p++)
            asm volatile("ldmatrix.sync.aligned.m8n8.x4.shared.b16 {%0,%1,%2,%3}, [%4];"
                         : "=r"(b[p][0]), "=r"(b[p][1]), "=r"(b[p][2]), "=r"(b[p][3])
                         : "r"(bAddr[p] + k0 * 4));
        #pragma unroll
        for (int mt = 0; mt < 2; mt++)
            #pragma unroll
            for (int nt = 0; nt < 4; nt++) {
                int p = nt >> 1, q = nt & 1;
                asm volatile(
                    "mma.sync.aligned.m16n8k8.row.col.f32.tf32.tf32.f32 "
                    "{%0,%1,%2,%3}, {%4,%5,%6,%7}, {%8,%9}, {%0,%1,%2,%3};"
                    : "+f"(acc[mt][nt][0]), "+f"(acc[mt][nt][1]),
                      "+f"(acc[mt][nt][2]), "+f"(acc[mt][nt][3])
                    : "r"(a[mt][0]), "r"(a[mt][1]), "r"(a[mt][2]), "r"(a[mt][3]),
                      "r"(b[p][q]), "r"(b[p][q + 2]));
            }
    }

    const int rbase = lane >> 2;
    const int col2  = (lane & 3) * 2;
    const bool isY  = (blockIdx.y < 8);

    #pragma unroll
    for (int mt = 0; mt < 2; mt++) {
        #pragma unroll
        for (int hh = 0; hh < 2; hh++) {
            int gm = m0 + wm * 32 + mt * 16 + rbase + hh * 8;
            if (gm >= M) continue;
            #pragma unroll
            for (int nt = 0; nt < 4; nt++) {
                int gn = n0 + wn * 32 + nt * 8 + col2;
                float c0 = acc[mt][nt][hh * 2];
                float c1 = acc[mt][nt][hh * 2 + 1];
                if (isY) {
                    *(__half2*)(g_Yh + (size_t)gm * 512 + gn) = __floats2half2_rn(c0, c1);
                } else {
                    int co = gn - 512;
                    float2 o;
                    o.x = c0 + bias[co];
                    o.y = c1 + bias[co + 1];
                    *(float2*)(out + (size_t)gm * HD + co) = o;
                }
            }
        }
    }
}

// ---------------------------------------------------------------------------
// CSR build
// ---------------------------------------------------------------------------
__global__ __launch_bounds__(256) void zero_k()
{
    int i = blockIdx.x * blockDim.x + threadIdx.x;
    if (i < NP) { g_cnt[i] = 0; g_cur[i] = 0; }
}

__global__ __launch_bounds__(256) void hist_k(const int* __restrict__ dst, int E)
{
    int e = blockIdx.x * blockDim.x + threadIdx.x;
    if (e < E) atomicAdd(&g_cnt[dst[e]], 1);
}

__global__ __launch_bounds__(256) void scan1_k()
{
    __shared__ int s[256];
    int t = threadIdx.x;
    int gid = blockIdx.x * 256 + t;
    int v = g_cnt[gid];
    s[t] = v;
    __syncthreads();
    #pragma unroll
    for (int d = 1; d < 256; d <<= 1) {
        int x = (t >= d) ? s[t - d] : 0;
        __syncthreads();
        s[t] += x;
        __syncthreads();
    }
    g_off[gid] = s[t] - v;               // exclusive within block
    if (t == 255) g_bsum[blockIdx.x] = s[t];
}

__global__ __launch_bounds__(256) void scan2_k()
{
    __shared__ int s[256];
    int t = threadIdx.x;
    int v = (t < NBLK) ? g_bsum[t] : 0;
    s[t] = v;
    __syncthreads();
    #pragma unroll
    for (int d = 1; d < 256; d <<= 1) {
        int x = (t >= d) ? s[t - d] : 0;
        __syncthreads();
        s[t] += x;
        __syncthreads();
    }
    if (t < NBLK) g_bscan[t] = s[t] - v;  // exclusive block offsets
}

__global__ __launch_bounds__(256) void scan3_k()
{
    int i = blockIdx.x * blockDim.x + threadIdx.x;
    if (i < NP) g_off[i] += g_bscan[i >> 8];
}

__global__ __launch_bounds__(256) void bucket_k(
    const float* __restrict__ w_comp,
    const float* __restrict__ norm,
    const int* __restrict__ src,
    const int* __restrict__ dst,
    const int* __restrict__ etype,
    int E)
{
    int e = blockIdx.x * blockDim.x + threadIdx.x;
    if (e >= E) return;
    int d = dst[e];
    int pos = g_off[d] + atomicAdd(&g_cur[d], 1);
    int t = etype[e];
    float nm = norm[e];
    float4 c;
    c.x = w_comp[t * NB + 0] * nm;
    c.y = w_comp[t * NB + 1] * nm;
    c.z = w_comp[t * NB + 2] * nm;
    c.w = w_comp[t * NB + 3] * nm;
    g_esrc[pos]  = src[e];
    g_ecoef[pos] = c;
}

// ---------------------------------------------------------------------------
// K_acc: warp per dst node; register accumulation; fused relu. No atomics.
// ---------------------------------------------------------------------------
struct alignas(8) Half4 { __half2 lo, hi; };

__global__ __launch_bounds__(256) void accum_k(float* __restrict__ out, int M)
{
    int v    = (blockIdx.x * blockDim.x + threadIdx.x) >> 5;
    int lane = threadIdx.x & 31;
    if (v >= M) return;

    int base = g_off[v];
    int deg  = g_cnt[v];

    float4 acc = *(const float4*)(out + (size_t)v * HD + lane * 4);

    const __half* Yl = g_Yh + lane * 4;
    for (int i = 0; i < deg; i++) {
        int s    = g_esrc[base + i];
        float4 c = g_ecoef[base + i];
        const __half* Y = Yl + (size_t)s * 512;
        Half4 v0 = *(const Half4*)(Y);
        Half4 v1 = *(const Half4*)(Y + 128);
        Half4 v2 = *(const Half4*)(Y + 256);
        Half4 v3 = *(const Half4*)(Y + 384);
        float2 l0 = __half22float2(v0.lo), h0 = __half22float2(v0.hi);
        float2 l1 = __half22float2(v1.lo), h1 = __half22float2(v1.hi);
        float2 l2 = __half22float2(v2.lo), h2 = __half22float2(v2.hi);
        float2 l3 = __half22float2(v3.lo), h3 = __half22float2(v3.hi);
        acc.x += c.x * l0.x + c.y * l1.x + c.z * l2.x + c.w * l3.x;
        acc.y += c.x * l0.y + c.y * l1.y + c.z * l2.y + c.w * l3.y;
        acc.z += c.x * h0.x + c.y * h1.x + c.z * h2.x + c.w * h3.x;
        acc.w += c.x * h0.y + c.y * h1.y + c.z * h2.y + c.w * h3.y;
    }

    acc.x = fmaxf(acc.x, 0.f);
    acc.y = fmaxf(acc.y, 0.f);
    acc.z = fmaxf(acc.z, 0.f);
    acc.w = fmaxf(acc.w, 0.f);
    *(float4*)(out + (size_t)v * HD + lane * 4) = acc;
}

extern "C" void kernel_launch(void* const* d_in, const int* in_sizes, int n_in,
                              void* d_out, int out_size)
{
    const float* h       = (const float*)d_in[0];
    const float* norm    = (const float*)d_in[1];
    const float* basis_w = (const float*)d_in[2];
    const float* w_comp  = (const float*)d_in[3];
    const float* loop_w  = (const float*)d_in[4];
    const float* bias    = (const float*)d_in[5];
    const int*   src     = (const int*)d_in[6];
    const int*   dst     = (const int*)d_in[7];
    const int*   etype   = (const int*)d_in[8];
    float* out = (float*)d_out;

    int M = in_sizes[0] / HD;   // 50000
    int E = in_sizes[6];        // 800000

    cudaFuncSetAttribute(gemm_tc, cudaFuncAttributeMaxDynamicSharedMemorySize, SMEM_BYTES);

    // weights + GEMM
    wt_transpose<<<(NCOLS * HD + 255) / 256, 256>>>(basis_w, loop_w);
    dim3 g1((M + 127) / 128, NCOLS / 64);
    gemm_tc<<<g1, 256, SMEM_BYTES>>>(h, bias, out, M);

    // CSR build (independent of GEMM; stream order serializes anyway)
    zero_k<<<NP / 256, 256>>>();
    hist_k<<<(E + 255) / 256, 256>>>(dst, E);
    scan1_k<<<NBLK, 256>>>();
    scan2_k<<<1, 256>>>();
    scan3_k<<<NP / 256, 256>>>();
    bucket_k<<<(E + 255) / 256, 256>>>(w_comp, norm, src, dst, etype, E);

    // accumulation + fused relu
    int warps = M;
    accum_k<<<(warps * 32 + 255) / 256, 256>>>(out, M);
}

// round 6
// speedup vs baseline: 2.3097x; 1.2862x over previous
#include <cuda_runtime.h>
#include <cuda_fp16.h>
#include <cstdint>

// RGCN basis layer, scatter-first ordering (matches reference contraction):
//   agg[v, b, :] = sum_{e: dst=v} (w_comp[etype_e, b] * norm_e) * h[src_e]
//   out = relu( [agg | h] @ [W0;W1;W2;W3;loop_w] + bias )
// Stages:
//   h16:    h -> fp16 copy (padded)
//   wt2:    WT2[n=128][k=640] tf32 n-major weight stack
//   CSR:    counts -> scan -> bucket (src, c0..c3) per dst
//   accum:  warp/dst register accumulation -> agg fp16 (no atomics)
//   gemm2:  tf32 tensor-core GEMM [NP,640]x[640,128], bias+relu fused

#define HD 128
#define NB 4
#define NNODES 50000
#define NEDGES 800000
#define NP 50176            // 392 * 128 = 196 * 256
#define NBLK 196
#define KTOT 640
#define SMS2 68             // smem row stride (floats): 272B, conflict-free ldmatrix

__device__ __half g_h16[(size_t)NP * HD];        // 12.8 MB
__device__ __half g_agg[(size_t)NP * 512];       // 51.4 MB
__device__ float  g_WT2[HD * KTOT];              // n-major weights, tf32-rounded

// CSR scratch
__device__ int    g_cnt[NP];
__device__ int    g_cur[NP];
__device__ int    g_off[NP];
__device__ int    g_bsum[NBLK];
__device__ int    g_bscan[NBLK];
__device__ int    g_esrc[NEDGES];
__device__ float4 g_ecoef[NEDGES];

static __device__ __forceinline__ uint32_t smem_u32(const void* p) {
    uint32_t a;
    asm("{ .reg .u64 t; cvta.to.shared.u64 t, %1; cvt.u32.u64 %0, t; }" : "=r"(a) : "l"(p));
    return a;
}

struct alignas(8) Half4 { __half2 lo, hi; };

// ---------------------------------------------------------------------------
// h -> fp16 (pad rows zero)
// ---------------------------------------------------------------------------
__global__ __launch_bounds__(256) void h16_k(const float* __restrict__ h, int M)
{
    int q = blockIdx.x * blockDim.x + threadIdx.x;   // float4 quad index
    if (q >= NP * 32) return;
    int m = q >> 5;
    float4 v = (m < M) ? *(const float4*)(h + (size_t)q * 4)
                       : make_float4(0.f, 0.f, 0.f, 0.f);
    Half4 o;
    o.lo = __floats2half2_rn(v.x, v.y);
    o.hi = __floats2half2_rn(v.z, v.w);
    *(Half4*)(g_h16 + (size_t)q * 4) = o;
}

// ---------------------------------------------------------------------------
// WT2[n][k] tf32: k<512 -> basis_w[k>>7][k&127][n]; else loop_w[k-512][n]
// ---------------------------------------------------------------------------
__global__ __launch_bounds__(256) void wt2_k(
    const float* __restrict__ basis_w, const float* __restrict__ loop_w)
{
    int idx = blockIdx.x * blockDim.x + threadIdx.x;
    if (idx >= HD * KTOT) return;
    int n = idx / KTOT;
    int k = idx - n * KTOT;
    float v;
    if (k < NB * HD) {
        int b = k >> 7, kk = k & 127;
        v = basis_w[(size_t)b * HD * HD + (size_t)kk * HD + n];
    } else {
        v = loop_w[(size_t)(k - NB * HD) * HD + n];
    }
    uint32_t t;
    asm("cvt.rna.tf32.f32 %0, %1;" : "=r"(t) : "f"(v));
    ((uint32_t*)g_WT2)[idx] = t;
}

// ---------------------------------------------------------------------------
// CSR build
// ---------------------------------------------------------------------------
__global__ __launch_bounds__(256) void zero_k()
{
    int i = blockIdx.x * blockDim.x + threadIdx.x;
    if (i < NP) { g_cnt[i] = 0; g_cur[i] = 0; }
}

__global__ __launch_bounds__(256) void hist_k(const int* __restrict__ dst, int E)
{
    int e = blockIdx.x * blockDim.x + threadIdx.x;
    if (e < E) atomicAdd(&g_cnt[dst[e]], 1);
}

__global__ __launch_bounds__(256) void scan1_k()
{
    __shared__ int s[256];
    int t = threadIdx.x;
    int gid = blockIdx.x * 256 + t;
    int v = g_cnt[gid];
    s[t] = v;
    __syncthreads();
    #pragma unroll
    for (int d = 1; d < 256; d <<= 1) {
        int x = (t >= d) ? s[t - d] : 0;
        __syncthreads();
        s[t] += x;
        __syncthreads();
    }
    g_off[gid] = s[t] - v;
    if (t == 255) g_bsum[blockIdx.x] = s[t];
}

__global__ __launch_bounds__(256) void scan2_k()
{
    __shared__ int s[256];
    int t = threadIdx.x;
    int v = (t < NBLK) ? g_bsum[t] : 0;
    s[t] = v;
    __syncthreads();
    #pragma unroll
    for (int d = 1; d < 256; d <<= 1) {
        int x = (t >= d) ? s[t - d] : 0;
        __syncthreads();
        s[t] += x;
        __syncthreads();
    }
    if (t < NBLK) g_bscan[t] = s[t] - v;
}

__global__ __launch_bounds__(256) void scan3_k()
{
    int i = blockIdx.x * blockDim.x + threadIdx.x;
    if (i < NP) g_off[i] += g_bscan[i >> 8];
}

__global__ __launch_bounds__(256) void bucket_k(
    const float* __restrict__ w_comp,
    const float* __restrict__ norm,
    const int* __restrict__ src,
    const int* __restrict__ dst,
    const int* __restrict__ etype,
    int E)
{
    int e = blockIdx.x * blockDim.x + threadIdx.x;
    if (e >= E) return;
    int d = dst[e];
    int pos = g_off[d] + atomicAdd(&g_cur[d], 1);
    int t = etype[e];
    float nm = norm[e];
    float4 c;
    c.x = w_comp[t * NB + 0] * nm;
    c.y = w_comp[t * NB + 1] * nm;
    c.z = w_comp[t * NB + 2] * nm;
    c.w = w_comp[t * NB + 3] * nm;
    g_esrc[pos]  = src[e];
    g_ecoef[pos] = c;
}

// ---------------------------------------------------------------------------
// accum: warp per dst node. 16 fp32 acc regs/lane (4 bases x 4 cols).
// Gathers 8B/lane of h16 per edge; writes agg fp16 once. No atomics.
// ---------------------------------------------------------------------------
__global__ __launch_bounds__(256) void accum_k()
{
    int v    = (blockIdx.x * blockDim.x + threadIdx.x) >> 5;
    int lane = threadIdx.x & 31;
    if (v >= NP) return;

    int base = g_off[v];
    int deg  = g_cnt[v];

    float4 a0 = {0.f, 0.f, 0.f, 0.f};
    float4 a1 = a0, a2 = a0, a3 = a0;

    const __half* Hl = g_h16 + lane * 4;
    for (int i = 0; i < deg; i++) {
        int s    = g_esrc[base + i];
        float4 c = g_ecoef[base + i];
        Half4 hv = *(const Half4*)(Hl + (size_t)s * HD);
        float2 lo = __half22float2(hv.lo);
        float2 hi = __half22float2(hv.hi);
        a0.x += c.x * lo.x; a0.y += c.x * lo.y; a0.z += c.x * hi.x; a0.w += c.x * hi.y;
        a1.x += c.y * lo.x; a1.y += c.y * lo.y; a1.z += c.y * hi.x; a1.w += c.y * hi.y;
        a2.x += c.z * lo.x; a2.y += c.z * lo.y; a2.z += c.z * hi.x; a2.w += c.z * hi.y;
        a3.x += c.w * lo.x; a3.y += c.w * lo.y; a3.z += c.w * hi.x; a3.w += c.w * hi.y;
    }

    __half* ap = g_agg + (size_t)v * 512 + lane * 4;
    Half4 o;
    o.lo = __floats2half2_rn(a0.x, a0.y); o.hi = __floats2half2_rn(a0.z, a0.w);
    *(Half4*)(ap + 0)   = o;
    o.lo = __floats2half2_rn(a1.x, a1.y); o.hi = __floats2half2_rn(a1.z, a1.w);
    *(Half4*)(ap + 128) = o;
    o.lo = __floats2half2_rn(a2.x, a2.y); o.hi = __floats2half2_rn(a2.z, a2.w);
    *(Half4*)(ap + 256) = o;
    o.lo = __floats2half2_rn(a3.x, a3.y); o.hi = __floats2half2_rn(a3.z, a3.w);
    *(Half4*)(ap + 384) = o;
}

// ---------------------------------------------------------------------------
// gemm2: tf32 mma. Block 128m x 128n, K=640 in chunks of 64.
// 8 warps = 4m x 2n; warp tile 32m x 64n; fused bias + relu epilogue.
// ---------------------------------------------------------------------------
#define SMEM_BYTES (2 * 128 * SMS2 * 4)

__global__ __launch_bounds__(256) void gemm2_k(
    const float* __restrict__ bias,
    float* __restrict__ out,
    int M)
{
    extern __shared__ float smf[];
    float* As = smf;               // [m=128][k=64 +pad]
    float* Bs = smf + 128 * SMS2;  // [n=128][k=64 +pad]

    const int tid  = threadIdx.x;
    const int m0   = blockIdx.x * 128;
    const int lane = tid & 31;
    const int w    = tid >> 5;
    const int wm   = w & 3;     // 32-row m slice
    const int wn   = w >> 2;    // 64-col n slice

    const int r8     = lane & 7;
    const int sel    = lane >> 3;
    const int rowoff = r8 + ((sel & 1) << 3);
    const int koff   = (sel & 2) ? 4 : 0;

    uint32_t aAddr[2], bAddr[4];
    #pragma unroll
    for (int mt = 0; mt < 2; mt++)
        aAddr[mt] = smem_u32(As + (wm * 32 + mt * 16 + rowoff) * SMS2 + koff);
    #pragma unroll
    for (int p = 0; p < 4; p++)
        bAddr[p] = smem_u32(Bs + (wn * 64 + p * 16 + rowoff) * SMS2 + koff);

    float acc[2][8][4];
    #pragma unroll
    for (int mt = 0; mt < 2; mt++)
        #pragma unroll
        for (int nt = 0; nt < 8; nt++)
            #pragma unroll
            for (int q = 0; q < 4; q++) acc[mt][nt][q] = 0.f;

    // fill indices: 16 quads per 64-col row
    const int fq_row = tid >> 4;        // 0..15 base row, step 16
    const int fq_c4  = tid & 15;        // quad in row

    for (int kc = 0; kc < 10; kc++) {
        int kbase = kc * 64;
        // ---- A fill: from g_agg (kc<8) else g_h16 ----
        if (kc < 8) {
            #pragma unroll
            for (int i = 0; i < 8; i++) {
                int r = fq_row + i * 16;
                const Half4 hv = *(const Half4*)(g_agg + (size_t)(m0 + r) * 512 + kbase + fq_c4 * 4);
                float2 lo = __half22float2(hv.lo);
                float2 hi = __half22float2(hv.hi);
                *(float4*)(As + r * SMS2 + fq_c4 * 4) = make_float4(lo.x, lo.y, hi.x, hi.y);
            }
        } else {
            #pragma unroll
            for (int i = 0; i < 8; i++) {
                int r = fq_row + i * 16;
                const Half4 hv = *(const Half4*)(g_h16 + (size_t)(m0 + r) * HD + (kbase - 512) + fq_c4 * 4);
                float2 lo = __half22float2(hv.lo);
                float2 hi = __half22float2(hv.hi);
                *(float4*)(As + r * SMS2 + fq_c4 * 4) = make_float4(lo.x, lo.y, hi.x, hi.y);
            }
        }
        // ---- B fill: WT2[n][640] ----
        #pragma unroll
        for (int i = 0; i < 8; i++) {
            int r = fq_row + i * 16;
            float4 v = *(const float4*)(g_WT2 + (size_t)r * KTOT + kbase + fq_c4 * 4);
            *(float4*)(Bs + r * SMS2 + fq_c4 * 4) = v;
        }
        __syncthreads();

        #pragma unroll
        for (int k0 = 0; k0 < 64; k0 += 8) {
            uint32_t a[2][4], b[4][4];
            #pragma unroll
            for (int mt = 0; mt < 2; mt++)
                asm volatile("ldmatrix.sync.aligned.m8n8.x4.shared.b16 {%0,%1,%2,%3}, [%4];"
                             : "=r"(a[mt][0]), "=r"(a[mt][1]), "=r"(a[mt][2]), "=r"(a[mt][3])
                             : "r"(aAddr[mt] + k0 * 4));
            #pragma unroll
            for (int p = 0; p < 4; p++)
                asm volatile("ldmatrix.sync.aligned.m8n8.x4.shared.b16 {%0,%1,%2,%3}, [%4];"
                             : "=r"(b[p][0]), "=r"(b[p][1]), "=r"(b[p][2]), "=r"(b[p][3])
                             : "r"(bAddr[p] + k0 * 4));
            #pragma unroll
            for (int mt = 0; mt < 2; mt++)
                #pragma unroll
                for (int nt = 0; nt < 8; nt++) {
                    int p = nt >> 1, q = nt & 1;
                    asm volatile(
                        "mma.sync.aligned.m16n8k8.row.col.f32.tf32.tf32.f32 "
                        "{%0,%1,%2,%3}, {%4,%5,%6,%7}, {%8,%9}, {%0,%1,%2,%3};"
                        : "+f"(acc[mt][nt][0]), "+f"(acc[mt][nt][1]),
                          "+f"(acc[mt][nt][2]), "+f"(acc[mt][nt][3])
                        : "r"(a[mt][0]), "r"(a[mt][1]), "r"(a[mt][2]), "r"(a[mt][3]),
                          "r"(b[p][q]), "r"(b[p][q + 2]));
                }
        }
        __syncthreads();
    }

    // ---- epilogue: bias + relu, write out ----
    const int rbase = lane >> 2;
    const int col2  = (lane & 3) * 2;
    #pragma unroll
    for (int mt = 0; mt < 2; mt++) {
        #pragma unroll
        for (int hh = 0; hh < 2; hh++) {
            int gm = m0 + wm * 32 + mt * 16 + rbase + hh * 8;
            if (gm >= M) continue;
            #pragma unroll
            for (int nt = 0; nt < 8; nt++) {
                int gn = wn * 64 + nt * 8 + col2;
                float2 o;
                o.x = fmaxf(acc[mt][nt][hh * 2]     + bias[gn],     0.f);
                o.y = fmaxf(acc[mt][nt][hh * 2 + 1] + bias[gn + 1], 0.f);
                *(float2*)(out + (size_t)gm * HD + gn) = o;
            }
        }
    }
}

extern "C" void kernel_launch(void* const* d_in, const int* in_sizes, int n_in,
                              void* d_out, int out_size)
{
    const float* h       = (const float*)d_in[0];
    const float* norm    = (const float*)d_in[1];
    const float* basis_w = (const float*)d_in[2];
    const float* w_comp  = (const float*)d_in[3];
    const float* loop_w  = (const float*)d_in[4];
    const float* bias    = (const float*)d_in[5];
    const int*   src     = (const int*)d_in[6];
    const int*   dst     = (const int*)d_in[7];
    const int*   etype   = (const int*)d_in[8];
    float* out = (float*)d_out;

    int M = in_sizes[0] / HD;   // 50000
    int E = in_sizes[6];        // 800000

    cudaFuncSetAttribute(gemm2_k, cudaFuncAttributeMaxDynamicSharedMemorySize, SMEM_BYTES);

    h16_k<<<(NP * 32 + 255) / 256, 256>>>(h, M);
    wt2_k<<<(HD * KTOT + 255) / 256, 256>>>(basis_w, loop_w);

    zero_k<<<NP / 256, 256>>>();
    hist_k<<<(E + 255) / 256, 256>>>(dst, E);
    scan1_k<<<NBLK, 256>>>();
    scan2_k<<<1, 256>>>();
    scan3_k<<<NP / 256, 256>>>();
    bucket_k<<<(E + 255) / 256, 256>>>(w_comp, norm, src, dst, etype, E);

    accum_k<<<(NP * 32 + 255) / 256, 256>>>();

    gemm2_k<<<NP / 128, 256, SMEM_BYTES>>>(bias, out, M);
}

// round 7
// speedup vs baseline: 2.7557x; 1.1931x over previous
#include <cuda_runtime.h>
#include <cuda_fp16.h>
#include <cstdint>

// RGCN basis layer, scatter-first ordering:
//   agg[v, b, :] = sum_{e: dst=v} (w_comp[etype_e, b] * norm_e) * h[src_e]
//   out = relu( [agg | h] @ [W0;W1;W2;W3;loop_w] + bias )
// Stages:
//   h16:    h -> fp16 copy (padded)
//   wt2:    Wh[n=128][k=640] fp16 n-major weight stack
//   CSR:    counts(+edge rank) -> scan -> bucket (src, c0..c3) per dst
//   accum:  warp/dst register accumulation -> agg fp16 (no atomics)
//   gemm2:  fp16 mma m16n8k16 (fp32 acc) [NP,640]x[640,128], bias+relu fused

#define HD 128
#define NB 4
#define NNODES 50000
#define NEDGES 800000
#define NP 50176            // 392 * 128 = 196 * 256
#define NBLK 196
#define KTOT 640
#define SMSH 72             // smem row stride in halves (144B) -> conflict-free ldmatrix

__device__ __half g_h16[(size_t)NP * HD];        // 12.8 MB
__device__ __half g_agg[(size_t)NP * 512];       // 51.4 MB
__device__ __half g_Wh[HD * KTOT];               // fp16 n-major weights

// CSR scratch
__device__ int    g_cnt[NP];
__device__ int    g_off[NP];
__device__ int    g_bsum[NBLK];
__device__ int    g_bscan[NBLK];
__device__ int    g_rank[NEDGES];
__device__ int    g_esrc[NEDGES];
__device__ float4 g_ecoef[NEDGES];

static __device__ __forceinline__ uint32_t smem_u32(const void* p) {
    uint32_t a;
    asm("{ .reg .u64 t; cvta.to.shared.u64 t, %1; cvt.u32.u64 %0, t; }" : "=r"(a) : "l"(p));
    return a;
}

struct alignas(8) Half4 { __half2 lo, hi; };

// ---------------------------------------------------------------------------
__global__ __launch_bounds__(256) void h16_k(const float* __restrict__ h, int M)
{
    int q = blockIdx.x * blockDim.x + threadIdx.x;   // float4 quad index
    if (q >= NP * 32) return;
    int m = q >> 5;
    float4 v = (m < M) ? *(const float4*)(h + (size_t)q * 4)
                       : make_float4(0.f, 0.f, 0.f, 0.f);
    Half4 o;
    o.lo = __floats2half2_rn(v.x, v.y);
    o.hi = __floats2half2_rn(v.z, v.w);
    *(Half4*)(g_h16 + (size_t)q * 4) = o;
}

// Wh[n][k]: k<512 -> basis_w[k>>7][k&127][n]; else loop_w[k-512][n]
__global__ __launch_bounds__(256) void wt2_k(
    const float* __restrict__ basis_w, const float* __restrict__ loop_w)
{
    int idx = blockIdx.x * blockDim.x + threadIdx.x;
    if (idx >= HD * KTOT) return;
    int n = idx / KTOT;
    int k = idx - n * KTOT;
    float v;
    if (k < NB * HD) {
        int b = k >> 7, kk = k & 127;
        v = basis_w[(size_t)b * HD * HD + (size_t)kk * HD + n];
    } else {
        v = loop_w[(size_t)(k - NB * HD) * HD + n];
    }
    g_Wh[idx] = __float2half_rn(v);
}

// ---------------------------------------------------------------------------
// CSR build
// ---------------------------------------------------------------------------
__global__ __launch_bounds__(256) void zero_k()
{
    int i = blockIdx.x * blockDim.x + threadIdx.x;
    if (i < NP) g_cnt[i] = 0;
}

__global__ __launch_bounds__(256) void hist_k(const int* __restrict__ dst, int E)
{
    int e = blockIdx.x * blockDim.x + threadIdx.x;
    if (e < E) g_rank[e] = atomicAdd(&g_cnt[dst[e]], 1);
}

__global__ __launch_bounds__(256) void scan1_k()
{
    __shared__ int s[256];
    int t = threadIdx.x;
    int gid = blockIdx.x * 256 + t;
    int v = g_cnt[gid];
    s[t] = v;
    __syncthreads();
    #pragma unroll
    for (int d = 1; d < 256; d <<= 1) {
        int x = (t >= d) ? s[t - d] : 0;
        __syncthreads();
        s[t] += x;
        __syncthreads();
    }
    g_off[gid] = s[t] - v;
    if (t == 255) g_bsum[blockIdx.x] = s[t];
}

__global__ __launch_bounds__(256) void scan2_k()
{
    __shared__ int s[256];
    int t = threadIdx.x;
    int v = (t < NBLK) ? g_bsum[t] : 0;
    s[t] = v;
    __syncthreads();
    #pragma unroll
    for (int d = 1; d < 256; d <<= 1) {
        int x = (t >= d) ? s[t - d] : 0;
        __syncthreads();
        s[t] += x;
        __syncthreads();
    }
    if (t < NBLK) g_bscan[t] = s[t] - v;
}

__global__ __launch_bounds__(256) void bucket_k(
    const float* __restrict__ w_comp,
    const float* __restrict__ norm,
    const int* __restrict__ src,
    const int* __restrict__ dst,
    const int* __restrict__ etype,
    int E)
{
    int e = blockIdx.x * blockDim.x + threadIdx.x;
    if (e >= E) return;
    int d = dst[e];
    int pos = g_off[d] + g_bscan[d >> 8] + g_rank[e];
    int t = etype[e];
    float nm = norm[e];
    float4 c;
    c.x = w_comp[t * NB + 0] * nm;
    c.y = w_comp[t * NB + 1] * nm;
    c.z = w_comp[t * NB + 2] * nm;
    c.w = w_comp[t * NB + 3] * nm;
    g_esrc[pos]  = src[e];
    g_ecoef[pos] = c;
}

// ---------------------------------------------------------------------------
// accum: warp per dst node. 16 fp32 acc regs/lane (4 bases x 4 cols).
// ---------------------------------------------------------------------------
__global__ __launch_bounds__(256) void accum_k()
{
    int v    = (blockIdx.x * blockDim.x + threadIdx.x) >> 5;
    int lane = threadIdx.x & 31;
    if (v >= NP) return;

    int base = g_off[v] + g_bscan[v >> 8];
    int deg  = g_cnt[v];

    float4 a0 = {0.f, 0.f, 0.f, 0.f};
    float4 a1 = a0, a2 = a0, a3 = a0;

    const __half* Hl = g_h16 + lane * 4;
    for (int i = 0; i < deg; i++) {
        int s    = g_esrc[base + i];
        float4 c = g_ecoef[base + i];
        Half4 hv = *(const Half4*)(Hl + (size_t)s * HD);
        float2 lo = __half22float2(hv.lo);
        float2 hi = __half22float2(hv.hi);
        a0.x += c.x * lo.x; a0.y += c.x * lo.y; a0.z += c.x * hi.x; a0.w += c.x * hi.y;
        a1.x += c.y * lo.x; a1.y += c.y * lo.y; a1.z += c.y * hi.x; a1.w += c.y * hi.y;
        a2.x += c.z * lo.x; a2.y += c.z * lo.y; a2.z += c.z * hi.x; a2.w += c.z * hi.y;
        a3.x += c.w * lo.x; a3.y += c.w * lo.y; a3.z += c.w * hi.x; a3.w += c.w * hi.y;
    }

    __half* ap = g_agg + (size_t)v * 512 + lane * 4;
    Half4 o;
    o.lo = __floats2half2_rn(a0.x, a0.y); o.hi = __floats2half2_rn(a0.z, a0.w);
    *(Half4*)(ap + 0)   = o;
    o.lo = __floats2half2_rn(a1.x, a1.y); o.hi = __floats2half2_rn(a1.z, a1.w);
    *(Half4*)(ap + 128) = o;
    o.lo = __floats2half2_rn(a2.x, a2.y); o.hi = __floats2half2_rn(a2.z, a2.w);
    *(Half4*)(ap + 256) = o;
    o.lo = __floats2half2_rn(a3.x, a3.y); o.hi = __floats2half2_rn(a3.z, a3.w);
    *(Half4*)(ap + 384) = o;
}

// ---------------------------------------------------------------------------
// gemm2: fp16 mma m16n8k16 (f32 acc). Block 128m x 128n, K=640 in 64-chunks.
// 8 warps = 4m x 2n; warp tile 32m x 64n; fused bias + relu epilogue.
// ---------------------------------------------------------------------------
#define SMEM_BYTES (2 * 128 * SMSH * 2)

__global__ __launch_bounds__(256) void gemm2_k(
    const float* __restrict__ bias,
    float* __restrict__ out,
    int M)
{
    extern __shared__ __half smh[];
    __half* As = smh;               // [m=128][k=64 +pad]
    __half* Bs = smh + 128 * SMSH;  // [n=128][k=64 +pad]

    const int tid  = threadIdx.x;
    const int m0   = blockIdx.x * 128;
    const int lane = tid & 31;
    const int w    = tid >> 5;
    const int wm   = w & 3;     // 32-row m slice
    const int wn   = w >> 2;    // 64-col n slice

    // A ldmatrix lanes: 0-7 rows0-7 k0-7 | 8-15 rows8-15 k0-7 | 16-23 rows0-7 k8-15 | 24-31 rows8-15 k8-15
    const int arow  = (lane & 7) + ((lane >> 3) & 1) * 8;
    const int akoff = (lane & 16) ? 8 : 0;
    // B ldmatrix lanes: 0-7 n0-7 k0-7 | 8-15 n0-7 k8-15 | 16-23 n8-15 k0-7 | 24-31 n8-15 k8-15
    const int brow  = (lane & 7) + ((lane & 16) ? 8 : 0);
    const int bkoff = (lane & 8) ? 8 : 0;

    uint32_t aAddr[2], bAddr[4];
    #pragma unroll
    for (int mt = 0; mt < 2; mt++)
        aAddr[mt] = smem_u32(As + (wm * 32 + mt * 16 + arow) * SMSH + akoff);
    #pragma unroll
    for (int p = 0; p < 4; p++)
        bAddr[p] = smem_u32(Bs + (wn * 64 + p * 16 + brow) * SMSH + bkoff);

    float acc[2][8][4];
    #pragma unroll
    for (int mt = 0; mt < 2; mt++)
        #pragma unroll
        for (int nt = 0; nt < 8; nt++)
            #pragma unroll
            for (int q = 0; q < 4; q++) acc[mt][nt][q] = 0.f;

    const int fr = tid >> 4;     // 0..15 base row, step 16
    const int fq = tid & 15;     // Half4 quad in 64-half row

    for (int kc = 0; kc < 10; kc++) {
        int kbase = kc * 64;
        if (kc < 8) {
            #pragma unroll
            for (int i = 0; i < 8; i++) {
                int r = fr + i * 16;
                *(Half4*)(As + r * SMSH + fq * 4) =
                    *(const Half4*)(g_agg + (size_t)(m0 + r) * 512 + kbase + fq * 4);
            }
        } else {
            #pragma unroll
            for (int i = 0; i < 8; i++) {
                int r = fr + i * 16;
                *(Half4*)(As + r * SMSH + fq * 4) =
                    *(const Half4*)(g_h16 + (size_t)(m0 + r) * HD + (kbase - 512) + fq * 4);
            }
        }
        #pragma unroll
        for (int i = 0; i < 8; i++) {
            int r = fr + i * 16;
            *(Half4*)(Bs + r * SMSH + fq * 4) =
                *(const Half4*)(g_Wh + (size_t)r * KTOT + kbase + fq * 4);
        }
        __syncthreads();

        #pragma unroll
        for (int k0 = 0; k0 < 64; k0 += 16) {
            uint32_t a[2][4], b[4][4];
            #pragma unroll
            for (int mt = 0; mt < 2; mt++)
                asm volatile("ldmatrix.sync.aligned.m8n8.x4.shared.b16 {%0,%1,%2,%3}, [%4];"
                             : "=r"(a[mt][0]), "=r"(a[mt][1]), "=r"(a[mt][2]), "=r"(a[mt][3])
                             : "r"(aAddr[mt] + k0 * 2));
            #pragma unroll
            for (int p = 0; p < 4; p++)
                asm volatile("ldmatrix.sync.aligned.m8n8.x4.shared.b16 {%0,%1,%2,%3}, [%4];"
                             : "=r"(b[p][0]), "=r"(b[p][1]), "=r"(b[p][2]), "=r"(b[p][3])
                             : "r"(bAddr[p] + k0 * 2));
            // b[p]: r0=b0(nt 2p), r1=b1(nt 2p), r2=b0(nt 2p+1), r3=b1(nt 2p+1)
            #pragma unroll
            for (int mt = 0; mt < 2; mt++)
                #pragma unroll
                for (int nt = 0; nt < 8; nt++) {
                    int p = nt >> 1, q = (nt & 1) * 2;
                    asm volatile(
                        "mma.sync.aligned.m16n8k16.row.col.f32.f16.f16.f32 "
                        "{%0,%1,%2,%3}, {%4,%5,%6,%7}, {%8,%9}, {%0,%1,%2,%3};"
                        : "+f"(acc[mt][nt][0]), "+f"(acc[mt][nt][1]),
                          "+f"(acc[mt][nt][2]), "+f"(acc[mt][nt][3])
                        : "r"(a[mt][0]), "r"(a[mt][1]), "r"(a[mt][2]), "r"(a[mt][3]),
                          "r"(b[p][q]), "r"(b[p][q + 1]));
                }
        }
        __syncthreads();
    }

    // ---- epilogue: bias + relu ----
    const int rbase = lane >> 2;
    const int col2  = (lane & 3) * 2;
    #pragma unroll
    for (int mt = 0; mt < 2; mt++) {
        #pragma unroll
        for (int hh = 0; hh < 2; hh++) {
            int gm = m0 + wm * 32 + mt * 16 + rbase + hh * 8;
            if (gm >= M) continue;
            #pragma unroll
            for (int nt = 0; nt < 8; nt++) {
                int gn = wn * 64 + nt * 8 + col2;
                float2 o;
                o.x = fmaxf(acc[mt][nt][hh * 2]     + bias[gn],     0.f);
                o.y = fmaxf(acc[mt][nt][hh * 2 + 1] + bias[gn + 1], 0.f);
                *(float2*)(out + (size_t)gm * HD + gn) = o;
            }
        }
    }
}

extern "C" void kernel_launch(void* const* d_in, const int* in_sizes, int n_in,
                              void* d_out, int out_size)
{
    const float* h       = (const float*)d_in[0];
    const float* norm    = (const float*)d_in[1];
    const float* basis_w = (const float*)d_in[2];
    const float* w_comp  = (const float*)d_in[3];
    const float* loop_w  = (const float*)d_in[4];
    const float* bias    = (const float*)d_in[5];
    const int*   src     = (const int*)d_in[6];
    const int*   dst     = (const int*)d_in[7];
    const int*   etype   = (const int*)d_in[8];
    float* out = (float*)d_out;

    int M = in_sizes[0] / HD;   // 50000
    int E = in_sizes[6];        // 800000

    cudaFuncSetAttribute(gemm2_k, cudaFuncAttributeMaxDynamicSharedMemorySize, SMEM_BYTES);

    h16_k<<<(NP * 32 + 255) / 256, 256>>>(h, M);
    wt2_k<<<(HD * KTOT + 255) / 256, 256>>>(basis_w, loop_w);

    zero_k<<<NP / 256, 256>>>();
    hist_k<<<(E + 255) / 256, 256>>>(dst, E);
    scan1_k<<<NBLK, 256>>>();
    scan2_k<<<1, 256>>>();
    bucket_k<<<(E + 255) / 256, 256>>>(w_comp, norm, src, dst, etype, E);

    accum_k<<<(NP * 32 + 255) / 256, 256>>>();

    gemm2_k<<<NP / 128, 256, SMEM_BYTES>>>(bias, out, M);
}

// round 8
// speedup vs baseline: 2.9891x; 1.0847x over previous
#include <cuda_runtime.h>
#include <cuda_fp16.h>
#include <cstdint>

// RGCN basis layer, scatter-first ordering:
//   agg[v, b, :] = sum_{e: dst=v} (w_comp[etype_e, b] * norm_e) * h[src_e]
//   out = relu( [agg | h] @ [W0;W1;W2;W3;loop_w] + bias )
// Stages:
//   prep:   h->fp16 copy, Wh fp16 n-major weight stack, zero counts (one kernel)
//   CSR:    hist (4 edges/thread, rank via atomic return) -> scan -> bucket
//   accum:  warp/dst register accumulation -> agg fp16 (no atomics, prefetch)
//   gemm2:  fp16 mma m16n8k16, cp.async 2-stage pipeline, bias+relu fused

#define HD 128
#define NB 4
#define NNODES 50000
#define NEDGES 800000
#define NP 50176            // 392 * 128 = 196 * 256
#define NBLK 196
#define KTOT 640
#define SMSH 72             // smem row stride in halves (144B) -> conflict-free ldmatrix

__device__ __half g_h16[(size_t)NP * HD];        // 12.8 MB
__device__ __half g_agg[(size_t)NP * 512];       // 51.4 MB
__device__ __half g_Wh[HD * KTOT];               // fp16 n-major weights

// CSR scratch
__device__ int    g_cnt[NP];
__device__ int    g_off[NP];
__device__ int    g_bsum[NBLK];
__device__ int    g_bscan[NBLK];
__device__ int    g_rank[NEDGES];
__device__ int    g_esrc[NEDGES];
__device__ float4 g_ecoef[NEDGES];

static __device__ __forceinline__ uint32_t smem_u32(const void* p) {
    uint32_t a;
    asm("{ .reg .u64 t; cvta.to.shared.u64 t, %1; cvt.u32.u64 %0, t; }" : "=r"(a) : "l"(p));
    return a;
}

#define CP_ASYNC8(sa, gp) \
    asm volatile("cp.async.ca.shared.global [%0], [%1], 8;" :: "r"(sa), "l"(gp))
#define CP_COMMIT() asm volatile("cp.async.commit_group;")

struct alignas(8) Half4 { __half2 lo, hi; };

// ---------------------------------------------------------------------------
// prep: h16 convert + weight stack + zero counts, one launch
// ---------------------------------------------------------------------------
__global__ __launch_bounds__(256) void prep_k(
    const float* __restrict__ h,
    const float* __restrict__ basis_w,
    const float* __restrict__ loop_w,
    int M)
{
    int idx = blockIdx.x * blockDim.x + threadIdx.x;

    if (idx < NP * 32) {            // h16: one float4 quad per thread
        int m = idx >> 5;
        float4 v = (m < M) ? *(const float4*)(h + (size_t)idx * 4)
                           : make_float4(0.f, 0.f, 0.f, 0.f);
        Half4 o;
        o.lo = __floats2half2_rn(v.x, v.y);
        o.hi = __floats2half2_rn(v.z, v.w);
        *(Half4*)(g_h16 + (size_t)idx * 4) = o;
    }
    if (idx < HD * KTOT) {          // Wh[n][k]
        int n = idx / KTOT;
        int k = idx - n * KTOT;
        float v;
        if (k < NB * HD) {
            int b = k >> 7, kk = k & 127;
            v = basis_w[(size_t)b * HD * HD + (size_t)kk * HD + n];
        } else {
            v = loop_w[(size_t)(k - NB * HD) * HD + n];
        }
        g_Wh[idx] = __float2half_rn(v);
    }
    if (idx < NP) g_cnt[idx] = 0;
}

// ---------------------------------------------------------------------------
// CSR build
// ---------------------------------------------------------------------------
__global__ __launch_bounds__(256) void hist_k(const int* __restrict__ dst, int E)
{
    int e0 = (blockIdx.x * blockDim.x + threadIdx.x) * 4;
    if (e0 + 3 < E) {
        int4 d = *(const int4*)(dst + e0);
        int r0 = atomicAdd(&g_cnt[d.x], 1);
        int r1 = atomicAdd(&g_cnt[d.y], 1);
        int r2 = atomicAdd(&g_cnt[d.z], 1);
        int r3 = atomicAdd(&g_cnt[d.w], 1);
        *(int4*)(g_rank + e0) = make_int4(r0, r1, r2, r3);
    } else {
        for (int e = e0; e < E; e++)
            g_rank[e] = atomicAdd(&g_cnt[dst[e]], 1);
    }
}

__global__ __launch_bounds__(256) void scan1_k()
{
    __shared__ int s[256];
    int t = threadIdx.x;
    int gid = blockIdx.x * 256 + t;
    int v = g_cnt[gid];
    s[t] = v;
    __syncthreads();
    #pragma unroll
    for (int d = 1; d < 256; d <<= 1) {
        int x = (t >= d) ? s[t - d] : 0;
        __syncthreads();
        s[t] += x;
        __syncthreads();
    }
    g_off[gid] = s[t] - v;
    if (t == 255) g_bsum[blockIdx.x] = s[t];
}

__global__ __launch_bounds__(256) void scan2_k()
{
    __shared__ int s[256];
    int t = threadIdx.x;
    int v = (t < NBLK) ? g_bsum[t] : 0;
    s[t] = v;
    __syncthreads();
    #pragma unroll
    for (int d = 1; d < 256; d <<= 1) {
        int x = (t >= d) ? s[t - d] : 0;
        __syncthreads();
        s[t] += x;
        __syncthreads();
    }
    if (t < NBLK) g_bscan[t] = s[t] - v;
}

__global__ __launch_bounds__(256) void bucket_k(
    const float* __restrict__ w_comp,
    const float* __restrict__ norm,
    const int* __restrict__ src,
    const int* __restrict__ dst,
    const int* __restrict__ etype,
    int E)
{
    int e0 = (blockIdx.x * blockDim.x + threadIdx.x) * 2;
    #pragma unroll
    for (int j = 0; j < 2; j++) {
        int e = e0 + j;
        if (e >= E) return;
        int d = dst[e];
        int pos = g_off[d] + g_bscan[d >> 8] + g_rank[e];
        int t = etype[e];
        float nm = norm[e];
        float4 c;
        c.x = w_comp[t * NB + 0] * nm;
        c.y = w_comp[t * NB + 1] * nm;
        c.z = w_comp[t * NB + 2] * nm;
        c.w = w_comp[t * NB + 3] * nm;
        g_esrc[pos]  = src[e];
        g_ecoef[pos] = c;
    }
}

// ---------------------------------------------------------------------------
// accum: warp per dst node; 16 fp32 acc regs/lane; next-edge prefetch.
// ---------------------------------------------------------------------------
__global__ __launch_bounds__(256) void accum_k()
{
    int v    = (blockIdx.x * blockDim.x + threadIdx.x) >> 5;
    int lane = threadIdx.x & 31;
    if (v >= NP) return;

    int base = g_off[v] + g_bscan[v >> 8];
    int deg  = g_cnt[v];

    float4 a0 = {0.f, 0.f, 0.f, 0.f};
    float4 a1 = a0, a2 = a0, a3 = a0;

    const __half* Hl = g_h16 + lane * 4;
    if (deg > 0) {
        int    sNext = g_esrc[base];
        float4 cNext = g_ecoef[base];
        for (int i = 1; i <= deg; i++) {
            int    s = sNext;
            float4 c = cNext;
            if (i < deg) {                 // prefetch next edge while gather lands
                sNext = g_esrc[base + i];
                cNext = g_ecoef[base + i];
            }
            Half4 hv = *(const Half4*)(Hl + (size_t)s * HD);
            float2 lo = __half22float2(hv.lo);
            float2 hi = __half22float2(hv.hi);
            a0.x += c.x * lo.x; a0.y += c.x * lo.y; a0.z += c.x * hi.x; a0.w += c.x * hi.y;
            a1.x += c.y * lo.x; a1.y += c.y * lo.y; a1.z += c.y * hi.x; a1.w += c.y * hi.y;
            a2.x += c.z * lo.x; a2.y += c.z * lo.y; a2.z += c.z * hi.x; a2.w += c.z * hi.y;
            a3.x += c.w * lo.x; a3.y += c.w * lo.y; a3.z += c.w * hi.x; a3.w += c.w * hi.y;
        }
    }

    __half* ap = g_agg + (size_t)v * 512 + lane * 4;
    Half4 o;
    o.lo = __floats2half2_rn(a0.x, a0.y); o.hi = __floats2half2_rn(a0.z, a0.w);
    *(Half4*)(ap + 0)   = o;
    o.lo = __floats2half2_rn(a1.x, a1.y); o.hi = __floats2half2_rn(a1.z, a1.w);
    *(Half4*)(ap + 128) = o;
    o.lo = __floats2half2_rn(a2.x, a2.y); o.hi = __floats2half2_rn(a2.z, a2.w);
    *(Half4*)(ap + 256) = o;
    o.lo = __floats2half2_rn(a3.x, a3.y); o.hi = __floats2half2_rn(a3.z, a3.w);
    *(Half4*)(ap + 384) = o;
}

// ---------------------------------------------------------------------------
// gemm2: fp16 mma m16n8k16, 2-stage cp.async pipeline.
// Block 128m x 128n, K=640 in 64-chunks; 8 warps = 4m x 2n.
// ---------------------------------------------------------------------------
#define STAGE_HALVES (2 * 128 * SMSH)              // A + B per stage
#define STAGE_BYTES  (STAGE_HALVES * 2)
#define SMEM_BYTES   (2 * STAGE_BYTES)             // 73728

__global__ __launch_bounds__(256) void gemm2_k(
    const float* __restrict__ bias,
    float* __restrict__ out,
    int M)
{
    extern __shared__ __half smh[];

    const int tid  = threadIdx.x;
    const int m0   = blockIdx.x * 128;
    const int lane = tid & 31;
    const int w    = tid >> 5;
    const int wm   = w & 3;
    const int wn   = w >> 2;

    const int fr = tid >> 4;     // 0..15 base row, step 16
    const int fq = tid & 15;     // Half4 quad in 64-half chunk row

    // per-thread smem fill addresses (stage 0)
    uint32_t sA0 = smem_u32(smh) + (uint32_t)(fr * SMSH + fq * 4) * 2;
    uint32_t sB0 = sA0 + (uint32_t)(128 * SMSH) * 2;

    // fill one 64-k chunk into stage s
    auto fill = [&](int kc, int s) {
        uint32_t sa = sA0 + s * STAGE_BYTES;
        uint32_t sb = sB0 + s * STAGE_BYTES;
        if (kc < 8) {
            const __half* ap = g_agg + (size_t)(m0 + fr) * 512 + kc * 64 + fq * 4;
            #pragma unroll
            for (int i = 0; i < 8; i++)
                CP_ASYNC8(sa + i * 16 * SMSH * 2, ap + (size_t)i * 16 * 512);
        } else {
            const __half* ap = g_h16 + (size_t)(m0 + fr) * HD + (kc * 64 - 512) + fq * 4;
            #pragma unroll
            for (int i = 0; i < 8; i++)
                CP_ASYNC8(sa + i * 16 * SMSH * 2, ap + (size_t)i * 16 * HD);
        }
        const __half* bp = g_Wh + (size_t)fr * KTOT + kc * 64 + fq * 4;
        #pragma unroll
        for (int i = 0; i < 8; i++)
            CP_ASYNC8(sb + i * 16 * SMSH * 2, bp + (size_t)i * 16 * KTOT);
        CP_COMMIT();
    };

    // ldmatrix lane addressing (stage 0 bases)
    const int arow  = (lane & 7) + ((lane >> 3) & 1) * 8;
    const int akoff = (lane & 16) ? 8 : 0;
    const int brow  = (lane & 7) + ((lane & 16) ? 8 : 0);
    const int bkoff = (lane & 8) ? 8 : 0;

    uint32_t aAddr[2], bAddr[4];
    #pragma unroll
    for (int mt = 0; mt < 2; mt++)
        aAddr[mt] = smem_u32(smh + (wm * 32 + mt * 16 + arow) * SMSH + akoff);
    #pragma unroll
    for (int p = 0; p < 4; p++)
        bAddr[p] = smem_u32(smh + 128 * SMSH + (wn * 64 + p * 16 + brow) * SMSH + bkoff);

    float acc[2][8][4];
    #pragma unroll
    for (int mt = 0; mt < 2; mt++)
        #pragma unroll
        for (int nt = 0; nt < 8; nt++)
            #pragma unroll
            for (int q = 0; q < 4; q++) acc[mt][nt][q] = 0.f;

    fill(0, 0);
    fill(1, 1);

    for (int kc = 0; kc < 10; kc++) {
        int s = kc & 1;
        if (kc == 9) { asm volatile("cp.async.wait_group 0;"); }
        else         { asm volatile("cp.async.wait_group 1;"); }
        __syncthreads();

        uint32_t soff = (uint32_t)s * STAGE_BYTES;
        #pragma unroll
        for (int k0 = 0; k0 < 64; k0 += 16) {
            uint32_t a[2][4], b[4][4];
            #pragma unroll
            for (int mt = 0; mt < 2; mt++)
                asm volatile("ldmatrix.sync.aligned.m8n8.x4.shared.b16 {%0,%1,%2,%3}, [%4];"
                             : "=r"(a[mt][0]), "=r"(a[mt][1]), "=r"(a[mt][2]), "=r"(a[mt][3])
                             : "r"(aAddr[mt] + soff + k0 * 2));
            #pragma unroll
            for (int p = 0; p < 4; p++)
                asm volatile("ldmatrix.sync.aligned.m8n8.x4.shared.b16 {%0,%1,%2,%3}, [%4];"
                             : "=r"(b[p][0]), "=r"(b[p][1]), "=r"(b[p][2]), "=r"(b[p][3])
                             : "r"(bAddr[p] + soff + k0 * 2));
            #pragma unroll
            for (int mt = 0; mt < 2; mt++)
                #pragma unroll
                for (int nt = 0; nt < 8; nt++) {
                    int p = nt >> 1, q = (nt & 1) * 2;
                    asm volatile(
                        "mma.sync.aligned.m16n8k16.row.col.f32.f16.f16.f32 "
                        "{%0,%1,%2,%3}, {%4,%5,%6,%7}, {%8,%9}, {%0,%1,%2,%3};"
                        : "+f"(acc[mt][nt][0]), "+f"(acc[mt][nt][1]),
                          "+f"(acc[mt][nt][2]), "+f"(acc[mt][nt][3])
                        : "r"(a[mt][0]), "r"(a[mt][1]), "r"(a[mt][2]), "r"(a[mt][3]),
                          "r"(b[p][q]), "r"(b[p][q + 1]));
                }
        }
        __syncthreads();
        if (kc + 2 < 10) fill(kc + 2, s);
    }

    // ---- epilogue: bias + relu ----
    const int rbase = lane >> 2;
    const int col2  = (lane & 3) * 2;
    #pragma unroll
    for (int mt = 0; mt < 2; mt++) {
        #pragma unroll
        for (int hh = 0; hh < 2; hh++) {
            int gm = m0 + wm * 32 + mt * 16 + rbase + hh * 8;
            if (gm >= M) continue;
            #pragma unroll
            for (int nt = 0; nt < 8; nt++) {
                int gn = wn * 64 + nt * 8 + col2;
                float2 o;
                o.x = fmaxf(acc[mt][nt][hh * 2]     + bias[gn],     0.f);
                o.y = fmaxf(acc[mt][nt][hh * 2 + 1] + bias[gn + 1], 0.f);
                *(float2*)(out + (size_t)gm * HD + gn) = o;
            }
        }
    }
}

extern "C" void kernel_launch(void* const* d_in, const int* in_sizes, int n_in,
                              void* d_out, int out_size)
{
    const float* h       = (const float*)d_in[0];
    const float* norm    = (const float*)d_in[1];
    const float* basis_w = (const float*)d_in[2];
    const float* w_comp  = (const float*)d_in[3];
    const float* loop_w  = (const float*)d_in[4];
    const float* bias    = (const float*)d_in[5];
    const int*   src     = (const int*)d_in[6];
    const int*   dst     = (const int*)d_in[7];
    const int*   etype   = (const int*)d_in[8];
    float* out = (float*)d_out;

    int M = in_sizes[0] / HD;   // 50000
    int E = in_sizes[6];        // 800000

    cudaFuncSetAttribute(gemm2_k, cudaFuncAttributeMaxDynamicSharedMemorySize, SMEM_BYTES);

    prep_k<<<(NP * 32 + 255) / 256, 256>>>(h, basis_w, loop_w, M);
    hist_k<<<((E + 3) / 4 + 255) / 256, 256>>>(dst, E);
    scan1_k<<<NBLK, 256>>>();
    scan2_k<<<1, 256>>>();
    bucket_k<<<((E + 1) / 2 + 255) / 256, 256>>>(w_comp, norm, src, dst, etype, E);
    accum_k<<<(NP * 32 + 255) / 256, 256>>>();
    gemm2_k<<<NP / 128, 256, SMEM_BYTES>>>(bias, out, M);
}

// round 9
// speedup vs baseline: 3.0228x; 1.0112x over previous
#include <cuda_runtime.h>
#include <cuda_fp16.h>
#include <cstdint>

// RGCN basis layer, scatter-first ordering:
//   agg[v, b, :] = sum_{e: dst=v} (w_comp[etype_e, b] * norm_e) * h[src_e]
//   out = relu( [agg | h] @ [W0;W1;W2;W3;loop_w] + bias )
// Stages:
//   prep:   h->fp16, Wh fp16 n-major stack, zero counts+total (one kernel)
//   hist:   per-dst counts + per-edge rank (4 edges/thread)
//   scan:   one kernel; block-local exclusive scan + atomic block base
//   bucket: (src, c0..c3) records per dst segment (4 edges/thread)
//   accum:  warp/dst register accumulation -> agg fp16 (2-edge unroll)
//   gemm2:  fp16 mma m16n8k16, cp.async 2-stage, 2 blocks/SM, bias+relu fused

#define HD 128
#define NB 4
#define NNODES 50000
#define NEDGES 800000
#define NP 50176            // 392 * 128 = 196 * 256
#define NBLK 196
#define KTOT 640
#define SMSH 72             // smem row stride in halves (144B) -> conflict-free ldmatrix

__device__ __half g_h16[(size_t)NP * HD];        // 12.8 MB
__device__ __half g_agg[(size_t)NP * 512];       // 51.4 MB
__device__ __half g_Wh[HD * KTOT];               // fp16 n-major weights

// CSR scratch
__device__ int    g_cnt[NP];
__device__ int    g_off[NP];
__device__ int    g_total;
__device__ int    g_rank[NEDGES];
__device__ int    g_esrc[NEDGES];
__device__ float4 g_ecoef[NEDGES];

static __device__ __forceinline__ uint32_t smem_u32(const void* p) {
    uint32_t a;
    asm("{ .reg .u64 t; cvta.to.shared.u64 t, %1; cvt.u32.u64 %0, t; }" : "=r"(a) : "l"(p));
    return a;
}

#define CP_ASYNC8(sa, gp) \
    asm volatile("cp.async.ca.shared.global [%0], [%1], 8;" :: "r"(sa), "l"(gp))
#define CP_COMMIT() asm volatile("cp.async.commit_group;")

struct alignas(8) Half4 { __half2 lo, hi; };

// ---------------------------------------------------------------------------
// prep: h16 convert + weight stack + zero counts
// ---------------------------------------------------------------------------
__global__ __launch_bounds__(256) void prep_k(
    const float* __restrict__ h,
    const float* __restrict__ basis_w,
    const float* __restrict__ loop_w,
    int M)
{
    int idx = blockIdx.x * blockDim.x + threadIdx.x;

    if (idx < NP * 32) {            // h16: one float4 quad per thread
        int m = idx >> 5;
        float4 v = (m < M) ? *(const float4*)(h + (size_t)idx * 4)
                           : make_float4(0.f, 0.f, 0.f, 0.f);
        Half4 o;
        o.lo = __floats2half2_rn(v.x, v.y);
        o.hi = __floats2half2_rn(v.z, v.w);
        *(Half4*)(g_h16 + (size_t)idx * 4) = o;
    }
    if (idx < HD * KTOT) {          // Wh[n][k]
        int n = idx / KTOT;
        int k = idx - n * KTOT;
        float v;
        if (k < NB * HD) {
            int b = k >> 7, kk = k & 127;
            v = basis_w[(size_t)b * HD * HD + (size_t)kk * HD + n];
        } else {
            v = loop_w[(size_t)(k - NB * HD) * HD + n];
        }
        g_Wh[idx] = __float2half_rn(v);
    }
    if (idx < NP) g_cnt[idx] = 0;
    if (idx == 0) g_total = 0;
}

// ---------------------------------------------------------------------------
// hist: counts + per-edge rank, 4 edges/thread for atomic MLP
// ---------------------------------------------------------------------------
__global__ __launch_bounds__(256) void hist_k(const int* __restrict__ dst, int E)
{
    int e0 = (blockIdx.x * blockDim.x + threadIdx.x) * 4;
    if (e0 + 3 < E) {
        int4 d = *(const int4*)(dst + e0);
        int r0 = atomicAdd(&g_cnt[d.x], 1);
        int r1 = atomicAdd(&g_cnt[d.y], 1);
        int r2 = atomicAdd(&g_cnt[d.z], 1);
        int r3 = atomicAdd(&g_cnt[d.w], 1);
        *(int4*)(g_rank + e0) = make_int4(r0, r1, r2, r3);
    } else {
        for (int e = e0; e < E; e++)
            g_rank[e] = atomicAdd(&g_cnt[dst[e]], 1);
    }
}

// ---------------------------------------------------------------------------
// scan: one kernel. Intra-block exclusive scan; block base via atomicAdd.
// Segment order across blocks is arbitrary (only disjointness is required).
// ---------------------------------------------------------------------------
__global__ __launch_bounds__(256) void scan_k()
{
    __shared__ int s[256];
    __shared__ int blockBase;
    int t = threadIdx.x;
    int gid = blockIdx.x * 256 + t;
    int v = g_cnt[gid];
    s[t] = v;
    __syncthreads();
    #pragma unroll
    for (int d = 1; d < 256; d <<= 1) {
        int x = (t >= d) ? s[t - d] : 0;
        __syncthreads();
        s[t] += x;
        __syncthreads();
    }
    if (t == 255) blockBase = atomicAdd(&g_total, s[255]);
    __syncthreads();
    g_off[gid] = blockBase + s[t] - v;
}

// ---------------------------------------------------------------------------
// bucket: 4 edges/thread, vector loads
// ---------------------------------------------------------------------------
__global__ __launch_bounds__(256) void bucket_k(
    const float* __restrict__ w_comp,
    const float* __restrict__ norm,
    const int* __restrict__ src,
    const int* __restrict__ dst,
    const int* __restrict__ etype,
    int E)
{
    int e0 = (blockIdx.x * blockDim.x + threadIdx.x) * 4;
    if (e0 + 3 < E) {
        int4   d = *(const int4*)(dst + e0);
        int4   sc = *(const int4*)(src + e0);
        int4   tt = *(const int4*)(etype + e0);
        float4 nm = *(const float4*)(norm + e0);
        int4   rk = *(const int4*)(g_rank + e0);
        int    dv[4] = {d.x, d.y, d.z, d.w};
        int    sv[4] = {sc.x, sc.y, sc.z, sc.w};
        int    tv[4] = {tt.x, tt.y, tt.z, tt.w};
        float  nv[4] = {nm.x, nm.y, nm.z, nm.w};
        int    rv[4] = {rk.x, rk.y, rk.z, rk.w};
        #pragma unroll
        for (int j = 0; j < 4; j++) {
            int pos = g_off[dv[j]] + rv[j];
            float4 c;
            c.x = w_comp[tv[j] * NB + 0] * nv[j];
            c.y = w_comp[tv[j] * NB + 1] * nv[j];
            c.z = w_comp[tv[j] * NB + 2] * nv[j];
            c.w = w_comp[tv[j] * NB + 3] * nv[j];
            g_esrc[pos]  = sv[j];
            g_ecoef[pos] = c;
        }
    } else {
        for (int e = e0; e < E; e++) {
            int dd = dst[e];
            int pos = g_off[dd] + g_rank[e];
            int t = etype[e];
            float nmv = norm[e];
            float4 c;
            c.x = w_comp[t * NB + 0] * nmv;
            c.y = w_comp[t * NB + 1] * nmv;
            c.z = w_comp[t * NB + 2] * nmv;
            c.w = w_comp[t * NB + 3] * nmv;
            g_esrc[pos]  = src[e];
            g_ecoef[pos] = c;
        }
    }
}

// ---------------------------------------------------------------------------
// accum: warp per dst node; 16 fp32 acc regs/lane; 2-edge unroll + prefetch.
// ---------------------------------------------------------------------------
__global__ __launch_bounds__(256) void accum_k()
{
    int v    = (blockIdx.x * blockDim.x + threadIdx.x) >> 5;
    int lane = threadIdx.x & 31;
    if (v >= NP) return;

    int base = g_off[v];
    int deg  = g_cnt[v];

    float4 a0 = {0.f, 0.f, 0.f, 0.f};
    float4 a1 = a0, a2 = a0, a3 = a0;

    const __half* Hl = g_h16 + lane * 4;
    int i = 0;
    for (; i + 2 <= deg; i += 2) {
        int    s0 = g_esrc[base + i];
        int    s1 = g_esrc[base + i + 1];
        float4 c0 = g_ecoef[base + i];
        float4 c1 = g_ecoef[base + i + 1];
        Half4 hv0 = *(const Half4*)(Hl + (size_t)s0 * HD);
        Half4 hv1 = *(const Half4*)(Hl + (size_t)s1 * HD);
        float2 lo0 = __half22float2(hv0.lo), hi0 = __half22float2(hv0.hi);
        float2 lo1 = __half22float2(hv1.lo), hi1 = __half22float2(hv1.hi);
        a0.x += c0.x * lo0.x + c1.x * lo1.x;  a0.y += c0.x * lo0.y + c1.x * lo1.y;
        a0.z += c0.x * hi0.x + c1.x * hi1.x;  a0.w += c0.x * hi0.y + c1.x * hi1.y;
        a1.x += c0.y * lo0.x + c1.y * lo1.x;  a1.y += c0.y * lo0.y + c1.y * lo1.y;
        a1.z += c0.y * hi0.x + c1.y * hi1.x;  a1.w += c0.y * hi0.y + c1.y * hi1.y;
        a2.x += c0.z * lo0.x + c1.z * lo1.x;  a2.y += c0.z * lo0.y + c1.z * lo1.y;
        a2.z += c0.z * hi0.x + c1.z * hi1.x;  a2.w += c0.z * hi0.y + c1.z * hi1.y;
        a3.x += c0.w * lo0.x + c1.w * lo1.x;  a3.y += c0.w * lo0.y + c1.w * lo1.y;
        a3.z += c0.w * hi0.x + c1.w * hi1.x;  a3.w += c0.w * hi0.y + c1.w * hi1.y;
    }
    if (i < deg) {
        int    s = g_esrc[base + i];
        float4 c = g_ecoef[base + i];
        Half4 hv = *(const Half4*)(Hl + (size_t)s * HD);
        float2 lo = __half22float2(hv.lo), hi = __half22float2(hv.hi);
        a0.x += c.x * lo.x; a0.y += c.x * lo.y; a0.z += c.x * hi.x; a0.w += c.x * hi.y;
        a1.x += c.y * lo.x; a1.y += c.y * lo.y; a1.z += c.y * hi.x; a1.w += c.y * hi.y;
        a2.x += c.z * lo.x; a2.y += c.z * lo.y; a2.z += c.z * hi.x; a2.w += c.z * hi.y;
        a3.x += c.w * lo.x; a3.y += c.w * lo.y; a3.z += c.w * hi.x; a3.w += c.w * hi.y;
    }

    __half* ap = g_agg + (size_t)v * 512 + lane * 4;
    Half4 o;
    o.lo = __floats2half2_rn(a0.x, a0.y); o.hi = __floats2half2_rn(a0.z, a0.w);
    *(Half4*)(ap + 0)   = o;
    o.lo = __floats2half2_rn(a1.x, a1.y); o.hi = __floats2half2_rn(a1.z, a1.w);
    *(Half4*)(ap + 128) = o;
    o.lo = __floats2half2_rn(a2.x, a2.y); o.hi = __floats2half2_rn(a2.z, a2.w);
    *(Half4*)(ap + 256) = o;
    o.lo = __floats2half2_rn(a3.x, a3.y); o.hi = __floats2half2_rn(a3.z, a3.w);
    *(Half4*)(ap + 384) = o;
}

// ---------------------------------------------------------------------------
// gemm2: fp16 mma m16n8k16, 2-stage cp.async pipeline, 2 blocks/SM.
// Block 128m x 128n, K=640 in 64-chunks; 8 warps = 4m x 2n.
// ---------------------------------------------------------------------------
#define STAGE_HALVES (2 * 128 * SMSH)              // A + B per stage
#define STAGE_BYTES  (STAGE_HALVES * 2)
#define SMEM_BYTES   (2 * STAGE_BYTES)             // 73728

__global__ __launch_bounds__(256, 2) void gemm2_k(
    const float* __restrict__ bias,
    float* __restrict__ out,
    int M)
{
    extern __shared__ __half smh[];

    const int tid  = threadIdx.x;
    const int m0   = blockIdx.x * 128;
    const int lane = tid & 31;
    const int w    = tid >> 5;
    const int wm   = w & 3;
    const int wn   = w >> 2;

    const int fr = tid >> 4;     // 0..15 base row, step 16
    const int fq = tid & 15;     // Half4 quad in 64-half chunk row

    uint32_t sA0 = smem_u32(smh) + (uint32_t)(fr * SMSH + fq * 4) * 2;
    uint32_t sB0 = sA0 + (uint32_t)(128 * SMSH) * 2;

    auto fill = [&](int kc, int s) {
        uint32_t sa = sA0 + s * STAGE_BYTES;
        uint32_t sb = sB0 + s * STAGE_BYTES;
        if (kc < 8) {
            const __half* ap = g_agg + (size_t)(m0 + fr) * 512 + kc * 64 + fq * 4;
            #pragma unroll
            for (int i = 0; i < 8; i++)
                CP_ASYNC8(sa + i * 16 * SMSH * 2, ap + (size_t)i * 16 * 512);
        } else {
            const __half* ap = g_h16 + (size_t)(m0 + fr) * HD + (kc * 64 - 512) + fq * 4;
            #pragma unroll
            for (int i = 0; i < 8; i++)
                CP_ASYNC8(sa + i * 16 * SMSH * 2, ap + (size_t)i * 16 * HD);
        }
        const __half* bp = g_Wh + (size_t)fr * KTOT + kc * 64 + fq * 4;
        #pragma unroll
        for (int i = 0; i < 8; i++)
            CP_ASYNC8(sb + i * 16 * SMSH * 2, bp + (size_t)i * 16 * KTOT);
        CP_COMMIT();
    };

    const int arow  = (lane & 7) + ((lane >> 3) & 1) * 8;
    const int akoff = (lane & 16) ? 8 : 0;
    const int brow  = (lane & 7) + ((lane & 16) ? 8 : 0);
    const int bkoff = (lane & 8) ? 8 : 0;

    uint32_t aAddr[2], bAddr[4];
    #pragma unroll
    for (int mt = 0; mt < 2; mt++)
        aAddr[mt] = smem_u32(smh + (wm * 32 + mt * 16 + arow) * SMSH + akoff);
    #pragma unroll
    for (int p = 0; p < 4; p++)
        bAddr[p] = smem_u32(smh + 128 * SMSH + (wn * 64 + p * 16 + brow) * SMSH + bkoff);

    float acc[2][8][4];
    #pragma unroll
    for (int mt = 0; mt < 2; mt++)
        #pragma unroll
        for (int nt = 0; nt < 8; nt++)
            #pragma unroll
            for (int q = 0; q < 4; q++) acc[mt][nt][q] = 0.f;

    fill(0, 0);
    fill(1, 1);

    for (int kc = 0; kc < 10; kc++) {
        int s = kc & 1;
        if (kc == 9) { asm volatile("cp.async.wait_group 0;"); }
        else         { asm volatile("cp.async.wait_group 1;"); }
        __syncthreads();

        uint32_t soff = (uint32_t)s * STAGE_BYTES;
        #pragma unroll
        for (int k0 = 0; k0 < 64; k0 += 16) {
            uint32_t a[2][4], b[4][4];
            #pragma unroll
            for (int mt = 0; mt < 2; mt++)
                asm volatile("ldmatrix.sync.aligned.m8n8.x4.shared.b16 {%0,%1,%2,%3}, [%4];"
                             : "=r"(a[mt][0]), "=r"(a[mt][1]), "=r"(a[mt][2]), "=r"(a[mt][3])
                             : "r"(aAddr[mt] + soff + k0 * 2));
            #pragma unroll
            for (int p = 0; p < 4; p++)
                asm volatile("ldmatrix.sync.aligned.m8n8.x4.shared.b16 {%0,%1,%2,%3}, [%4];"
                             : "=r"(b[p][0]), "=r"(b[p][1]), "=r"(b[p][2]), "=r"(b[p][3])
                             : "r"(bAddr[p] + soff + k0 * 2));
            #pragma unroll
            for (int mt = 0; mt < 2; mt++)
                #pragma unroll
                for (int nt = 0; nt < 8; nt++) {
                    int p = nt >> 1, q = (nt & 1) * 2;
                    asm volatile(
                        "mma.sync.aligned.m16n8k16.row.col.f32.f16.f16.f32 "
                        "{%0,%1,%2,%3}, {%4,%5,%6,%7}, {%8,%9}, {%0,%1,%2,%3};"
                        : "+f"(acc[mt][nt][0]), "+f"(acc[mt][nt][1]),
                          "+f"(acc[mt][nt][2]), "+f"(acc[mt][nt][3])
                        : "r"(a[mt][0]), "r"(a[mt][1]), "r"(a[mt][2]), "r"(a[mt][3]),
                          "r"(b[p][q]), "r"(b[p][q + 1]));
                }
        }
        __syncthreads();
        if (kc + 2 < 10) fill(kc + 2, s);
    }

    // ---- epilogue: bias + relu ----
    const int rbase = lane >> 2;
    const int col2  = (lane & 3) * 2;
    #pragma unroll
    for (int mt = 0; mt < 2; mt++) {
        #pragma unroll
        for (int hh = 0; hh < 2; hh++) {
            int gm = m0 + wm * 32 + mt * 16 + rbase + hh * 8;
            if (gm >= M) continue;
            #pragma unroll
            for (int nt = 0; nt < 8; nt++) {
                int gn = wn * 64 + nt * 8 + col2;
                float2 o;
                o.x = fmaxf(acc[mt][nt][hh * 2]     + bias[gn],     0.f);
                o.y = fmaxf(acc[mt][nt][hh * 2 + 1] + bias[gn + 1], 0.f);
                *(float2*)(out + (size_t)gm * HD + gn) = o;
            }
        }
    }
}

extern "C" void kernel_launch(void* const* d_in, const int* in_sizes, int n_in,
                              void* d_out, int out_size)
{
    const float* h       = (const float*)d_in[0];
    const float* norm    = (const float*)d_in[1];
    const float* basis_w = (const float*)d_in[2];
    const float* w_comp  = (const float*)d_in[3];
    const float* loop_w  = (const float*)d_in[4];
    const float* bias    = (const float*)d_in[5];
    const int*   src     = (const int*)d_in[6];
    const int*   dst     = (const int*)d_in[7];
    const int*   etype   = (const int*)d_in[8];
    float* out = (float*)d_out;

    int M = in_sizes[0] / HD;   // 50000
    int E = in_sizes[6];        // 800000

    cudaFuncSetAttribute(gemm2_k, cudaFuncAttributeMaxDynamicSharedMemorySize, SMEM_BYTES);

    prep_k<<<(NP * 32 + 255) / 256, 256>>>(h, basis_w, loop_w, M);
    hist_k<<<((E + 3) / 4 + 255) / 256, 256>>>(dst, E);
    scan_k<<<NBLK, 256>>>();
    bucket_k<<<((E + 3) / 4 + 255) / 256, 256>>>(w_comp, norm, src, dst, etype, E);
    accum_k<<<(NP * 32 + 255) / 256, 256>>>();
    gemm2_k<<<NP / 128, 256, SMEM_BYTES>>>(bias, out, M);
}

// round 10
// speedup vs baseline: 3.0746x; 1.0172x over previous
#include <cuda_runtime.h>
#include <cuda_fp16.h>
#include <cstdint>

// RGCN basis layer, scatter-first ordering:
//   agg[v, b, :] = sum_{e: dst=v} (w_comp[etype_e, b] * norm_e) * h[src_e]
//   out = relu( [agg | h] @ [W0;W1;W2;W3;loop_w] + bias )
// Stages:
//   prep:   h->fp16, Wh fp16 n-major stack, zero counts+total (one kernel)
//   hist:   per-dst counts + per-edge rank (4 edges/thread)
//   scan:   one kernel; block-local exclusive scan + atomic block base
//   bucket: ONE 16B record {src, c01h, c23h} per edge (single STG.128)
//   accum:  warp/dst register accumulation -> agg fp16 (4-edge unroll)
//   gemm2:  fp16 mma m16n8k16, cp.async 2-stage, 2 blocks/SM, bias+relu fused

#define HD 128
#define NB 4
#define NNODES 50000
#define NEDGES 800000
#define NP 50176            // 392 * 128 = 196 * 256
#define NBLK 196
#define KTOT 640
#define SMSH 72             // smem row stride in halves (144B) -> conflict-free ldmatrix

__device__ __half g_h16[(size_t)NP * HD];        // 12.8 MB
__device__ __half g_agg[(size_t)NP * 512];       // 51.4 MB
__device__ __half g_Wh[HD * KTOT];               // fp16 n-major weights

// CSR scratch
__device__ int  g_cnt[NP];
__device__ int  g_off[NP];
__device__ int  g_total;
__device__ int  g_rank[NEDGES];
__device__ int4 g_edge[NEDGES];    // {src, c01(half2), c23(half2), pad}

static __device__ __forceinline__ uint32_t smem_u32(const void* p) {
    uint32_t a;
    asm("{ .reg .u64 t; cvta.to.shared.u64 t, %1; cvt.u32.u64 %0, t; }" : "=r"(a) : "l"(p));
    return a;
}

#define CP_ASYNC8(sa, gp) \
    asm volatile("cp.async.ca.shared.global [%0], [%1], 8;" :: "r"(sa), "l"(gp))
#define CP_COMMIT() asm volatile("cp.async.commit_group;")

struct alignas(8) Half4 { __half2 lo, hi; };

static __device__ __forceinline__ int h2_as_int(__half2 h) {
    return *(int*)&h;
}
static __device__ __forceinline__ __half2 int_as_h2(int i) {
    return *(__half2*)&i;
}

// ---------------------------------------------------------------------------
// prep: h16 convert + weight stack + zero counts
// ---------------------------------------------------------------------------
__global__ __launch_bounds__(256) void prep_k(
    const float* __restrict__ h,
    const float* __restrict__ basis_w,
    const float* __restrict__ loop_w,
    int M)
{
    int idx = blockIdx.x * blockDim.x + threadIdx.x;

    if (idx < NP * 32) {            // h16: one float4 quad per thread
        int m = idx >> 5;
        float4 v = (m < M) ? *(const float4*)(h + (size_t)idx * 4)
                           : make_float4(0.f, 0.f, 0.f, 0.f);
        Half4 o;
        o.lo = __floats2half2_rn(v.x, v.y);
        o.hi = __floats2half2_rn(v.z, v.w);
        *(Half4*)(g_h16 + (size_t)idx * 4) = o;
    }
    if (idx < HD * KTOT) {          // Wh[n][k]
        int n = idx / KTOT;
        int k = idx - n * KTOT;
        float v;
        if (k < NB * HD) {
            int b = k >> 7, kk = k & 127;
            v = basis_w[(size_t)b * HD * HD + (size_t)kk * HD + n];
        } else {
            v = loop_w[(size_t)(k - NB * HD) * HD + n];
        }
        g_Wh[idx] = __float2half_rn(v);
    }
    if (idx < NP) g_cnt[idx] = 0;
    if (idx == 0) g_total = 0;
}

// ---------------------------------------------------------------------------
// hist: counts + per-edge rank, 4 edges/thread for atomic MLP
// ---------------------------------------------------------------------------
__global__ __launch_bounds__(256) void hist_k(const int* __restrict__ dst, int E)
{
    int e0 = (blockIdx.x * blockDim.x + threadIdx.x) * 4;
    if (e0 + 3 < E) {
        int4 d = *(const int4*)(dst + e0);
        int r0 = atomicAdd(&g_cnt[d.x], 1);
        int r1 = atomicAdd(&g_cnt[d.y], 1);
        int r2 = atomicAdd(&g_cnt[d.z], 1);
        int r3 = atomicAdd(&g_cnt[d.w], 1);
        *(int4*)(g_rank + e0) = make_int4(r0, r1, r2, r3);
    } else {
        for (int e = e0; e < E; e++)
            g_rank[e] = atomicAdd(&g_cnt[dst[e]], 1);
    }
}

// ---------------------------------------------------------------------------
// scan: block-local exclusive scan; base via atomicAdd (segment order arbitrary)
// ---------------------------------------------------------------------------
__global__ __launch_bounds__(256) void scan_k()
{
    __shared__ int s[256];
    __shared__ int blockBase;
    int t = threadIdx.x;
    int gid = blockIdx.x * 256 + t;
    int v = g_cnt[gid];
    s[t] = v;
    __syncthreads();
    #pragma unroll
    for (int d = 1; d < 256; d <<= 1) {
        int x = (t >= d) ? s[t - d] : 0;
        __syncthreads();
        s[t] += x;
        __syncthreads();
    }
    if (t == 255) blockBase = atomicAdd(&g_total, s[255]);
    __syncthreads();
    g_off[gid] = blockBase + s[t] - v;
}

// ---------------------------------------------------------------------------
// bucket: one 16B record per edge, single scattered STG.128
// ---------------------------------------------------------------------------
__global__ __launch_bounds__(256) void bucket_k(
    const float* __restrict__ w_comp,
    const float* __restrict__ norm,
    const int* __restrict__ src,
    const int* __restrict__ dst,
    const int* __restrict__ etype,
    int E)
{
    int e0 = (blockIdx.x * blockDim.x + threadIdx.x) * 4;
    if (e0 + 3 < E) {
        int4   d  = *(const int4*)(dst + e0);
        int4   sc = *(const int4*)(src + e0);
        int4   tt = *(const int4*)(etype + e0);
        float4 nm = *(const float4*)(norm + e0);
        int4   rk = *(const int4*)(g_rank + e0);
        int   dv[4] = {d.x, d.y, d.z, d.w};
        int   sv[4] = {sc.x, sc.y, sc.z, sc.w};
        int   tv[4] = {tt.x, tt.y, tt.z, tt.w};
        float nv[4] = {nm.x, nm.y, nm.z, nm.w};
        int   rv[4] = {rk.x, rk.y, rk.z, rk.w};
        #pragma unroll
        for (int j = 0; j < 4; j++) {
            const float* wr = w_comp + tv[j] * NB;
            __half2 c01 = __floats2half2_rn(wr[0] * nv[j], wr[1] * nv[j]);
            __half2 c23 = __floats2half2_rn(wr[2] * nv[j], wr[3] * nv[j]);
            g_edge[g_off[dv[j]] + rv[j]] =
                make_int4(sv[j], h2_as_int(c01), h2_as_int(c23), 0);
        }
    } else {
        for (int e = e0; e < E; e++) {
            int dd = dst[e];
            const float* wr = w_comp + etype[e] * NB;
            float nmv = norm[e];
            __half2 c01 = __floats2half2_rn(wr[0] * nmv, wr[1] * nmv);
            __half2 c23 = __floats2half2_rn(wr[2] * nmv, wr[3] * nmv);
            g_edge[g_off[dd] + g_rank[e]] =
                make_int4(src[e], h2_as_int(c01), h2_as_int(c23), 0);
        }
    }
}

// ---------------------------------------------------------------------------
// accum: warp per dst node; 16 fp32 acc regs/lane; 4-edge unroll (MLP 4).
// ---------------------------------------------------------------------------
__global__ __launch_bounds__(256) void accum_k()
{
    int v    = (blockIdx.x * blockDim.x + threadIdx.x) >> 5;
    int lane = threadIdx.x & 31;
    if (v >= NP) return;

    int base = g_off[v];
    int deg  = g_cnt[v];

    float4 a0 = {0.f, 0.f, 0.f, 0.f};
    float4 a1 = a0, a2 = a0, a3 = a0;

    const __half* Hl = g_h16 + lane * 4;

    int i = 0;
    for (; i + 4 <= deg; i += 4) {
        int4 r0 = g_edge[base + i];
        int4 r1 = g_edge[base + i + 1];
        int4 r2 = g_edge[base + i + 2];
        int4 r3 = g_edge[base + i + 3];
        Half4 hv0 = *(const Half4*)(Hl + (size_t)r0.x * HD);
        Half4 hv1 = *(const Half4*)(Hl + (size_t)r1.x * HD);
        Half4 hv2 = *(const Half4*)(Hl + (size_t)r2.x * HD);
        Half4 hv3 = *(const Half4*)(Hl + (size_t)r3.x * HD);
        #pragma unroll
        for (int j = 0; j < 4; j++) {
            int4 rr = (j == 0) ? r0 : (j == 1) ? r1 : (j == 2) ? r2 : r3;
            Half4 hh = (j == 0) ? hv0 : (j == 1) ? hv1 : (j == 2) ? hv2 : hv3;
            float2 c01 = __half22float2(int_as_h2(rr.y));
            float2 c23 = __half22float2(int_as_h2(rr.z));
            float2 lo = __half22float2(hh.lo), hi = __half22float2(hh.hi);
            a0.x += c01.x * lo.x; a0.y += c01.x * lo.y; a0.z += c01.x * hi.x; a0.w += c01.x * hi.y;
            a1.x += c01.y * lo.x; a1.y += c01.y * lo.y; a1.z += c01.y * hi.x; a1.w += c01.y * hi.y;
            a2.x += c23.x * lo.x; a2.y += c23.x * lo.y; a2.z += c23.x * hi.x; a2.w += c23.x * hi.y;
            a3.x += c23.y * lo.x; a3.y += c23.y * lo.y; a3.z += c23.y * hi.x; a3.w += c23.y * hi.y;
        }
    }
    for (; i < deg; i++) {
        int4 rr = g_edge[base + i];
        Half4 hh = *(const Half4*)(Hl + (size_t)rr.x * HD);
        float2 c01 = __half22float2(int_as_h2(rr.y));
        float2 c23 = __half22float2(int_as_h2(rr.z));
        float2 lo = __half22float2(hh.lo), hi = __half22float2(hh.hi);
        a0.x += c01.x * lo.x; a0.y += c01.x * lo.y; a0.z += c01.x * hi.x; a0.w += c01.x * hi.y;
        a1.x += c01.y * lo.x; a1.y += c01.y * lo.y; a1.z += c01.y * hi.x; a1.w += c01.y * hi.y;
        a2.x += c23.x * lo.x; a2.y += c23.x * lo.y; a2.z += c23.x * hi.x; a2.w += c23.x * hi.y;
        a3.x += c23.y * lo.x; a3.y += c23.y * lo.y; a3.z += c23.y * hi.x; a3.w += c23.y * hi.y;
    }

    __half* ap = g_agg + (size_t)v * 512 + lane * 4;
    Half4 o;
    o.lo = __floats2half2_rn(a0.x, a0.y); o.hi = __floats2half2_rn(a0.z, a0.w);
    *(Half4*)(ap + 0)   = o;
    o.lo = __floats2half2_rn(a1.x, a1.y); o.hi = __floats2half2_rn(a1.z, a1.w);
    *(Half4*)(ap + 128) = o;
    o.lo = __floats2half2_rn(a2.x, a2.y); o.hi = __floats2half2_rn(a2.z, a2.w);
    *(Half4*)(ap + 256) = o;
    o.lo = __floats2half2_rn(a3.x, a3.y); o.hi = __floats2half2_rn(a3.z, a3.w);
    *(Half4*)(ap + 384) = o;
}

// ---------------------------------------------------------------------------
// gemm2: fp16 mma m16n8k16, 2-stage cp.async pipeline, 2 blocks/SM.
// Block 128m x 128n, K=640 in 64-chunks; 8 warps = 4m x 2n.
// ---------------------------------------------------------------------------
#define STAGE_HALVES (2 * 128 * SMSH)              // A + B per stage
#define STAGE_BYTES  (STAGE_HALVES * 2)
#define SMEM_BYTES   (2 * STAGE_BYTES)             // 73728

__global__ __launch_bounds__(256, 2) void gemm2_k(
    const float* __restrict__ bias,
    float* __restrict__ out,
    int M)
{
    extern __shared__ __half smh[];

    const int tid  = threadIdx.x;
    const int m0   = blockIdx.x * 128;
    const int lane = tid & 31;
    const int w    = tid >> 5;
    const int wm   = w & 3;
    const int wn   = w >> 2;

    const int fr = tid >> 4;     // 0..15 base row, step 16
    const int fq = tid & 15;     // Half4 quad in 64-half chunk row

    uint32_t sA0 = smem_u32(smh) + (uint32_t)(fr * SMSH + fq * 4) * 2;
    uint32_t sB0 = sA0 + (uint32_t)(128 * SMSH) * 2;

    auto fill = [&](int kc, int s) {
        uint32_t sa = sA0 + s * STAGE_BYTES;
        uint32_t sb = sB0 + s * STAGE_BYTES;
        if (kc < 8) {
            const __half* ap = g_agg + (size_t)(m0 + fr) * 512 + kc * 64 + fq * 4;
            #pragma unroll
            for (int i = 0; i < 8; i++)
                CP_ASYNC8(sa + i * 16 * SMSH * 2, ap + (size_t)i * 16 * 512);
        } else {
            const __half* ap = g_h16 + (size_t)(m0 + fr) * HD + (kc * 64 - 512) + fq * 4;
            #pragma unroll
            for (int i = 0; i < 8; i++)
                CP_ASYNC8(sa + i * 16 * SMSH * 2, ap + (size_t)i * 16 * HD);
        }
        const __half* bp = g_Wh + (size_t)fr * KTOT + kc * 64 + fq * 4;
        #pragma unroll
        for (int i = 0; i < 8; i++)
            CP_ASYNC8(sb + i * 16 * SMSH * 2, bp + (size_t)i * 16 * KTOT);
        CP_COMMIT();
    };

    const int arow  = (lane & 7) + ((lane >> 3) & 1) * 8;
    const int akoff = (lane & 16) ? 8 : 0;
    const int brow  = (lane & 7) + ((lane & 16) ? 8 : 0);
    const int bkoff = (lane & 8) ? 8 : 0;

    uint32_t aAddr[2], bAddr[4];
    #pragma unroll
    for (int mt = 0; mt < 2; mt++)
        aAddr[mt] = smem_u32(smh + (wm * 32 + mt * 16 + arow) * SMSH + akoff);
    #pragma unroll
    for (int p = 0; p < 4; p++)
        bAddr[p] = smem_u32(smh + 128 * SMSH + (wn * 64 + p * 16 + brow) * SMSH + bkoff);

    float acc[2][8][4];
    #pragma unroll
    for (int mt = 0; mt < 2; mt++)
        #pragma unroll
        for (int nt = 0; nt < 8; nt++)
            #pragma unroll
            for (int q = 0; q < 4; q++) acc[mt][nt][q] = 0.f;

    fill(0, 0);
    fill(1, 1);

    for (int kc = 0; kc < 10; kc++) {
        int s = kc & 1;
        if (kc == 9) { asm volatile("cp.async.wait_group 0;"); }
        else         { asm volatile("cp.async.wait_group 1;"); }
        __syncthreads();

        uint32_t soff = (uint32_t)s * STAGE_BYTES;
        #pragma unroll
        for (int k0 = 0; k0 < 64; k0 += 16) {
            uint32_t a[2][4], b[4][4];
            #pragma unroll
            for (int mt = 0; mt < 2; mt++)
                asm volatile("ldmatrix.sync.aligned.m8n8.x4.shared.b16 {%0,%1,%2,%3}, [%4];"
                             : "=r"(a[mt][0]), "=r"(a[mt][1]), "=r"(a[mt][2]), "=r"(a[mt][3])
                             : "r"(aAddr[mt] + soff + k0 * 2));
            #pragma unroll
            for (int p = 0; p < 4; p++)
                asm volatile("ldmatrix.sync.aligned.m8n8.x4.shared.b16 {%0,%1,%2,%3}, [%4];"
                             : "=r"(b[p][0]), "=r"(b[p][1]), "=r"(b[p][2]), "=r"(b[p][3])
                             : "r"(bAddr[p] + soff + k0 * 2));
            #pragma unroll
            for (int mt = 0; mt < 2; mt++)
                #pragma unroll
                for (int nt = 0; nt < 8; nt++) {
                    int p = nt >> 1, q = (nt & 1) * 2;
                    asm volatile(
                        "mma.sync.aligned.m16n8k16.row.col.f32.f16.f16.f32 "
                        "{%0,%1,%2,%3}, {%4,%5,%6,%7}, {%8,%9}, {%0,%1,%2,%3};"
                        : "+f"(acc[mt][nt][0]), "+f"(acc[mt][nt][1]),
                          "+f"(acc[mt][nt][2]), "+f"(acc[mt][nt][3])
                        : "r"(a[mt][0]), "r"(a[mt][1]), "r"(a[mt][2]), "r"(a[mt][3]),
                          "r"(b[p][q]), "r"(b[p][q + 1]));
                }
        }
        __syncthreads();
        if (kc + 2 < 10) fill(kc + 2, s);
    }

    // ---- epilogue: bias + relu ----
    const int rbase = lane >> 2;
    const int col2  = (lane & 3) * 2;
    #pragma unroll
    for (int mt = 0; mt < 2; mt++) {
        #pragma unroll
        for (int hh = 0; hh < 2; hh++) {
            int gm = m0 + wm * 32 + mt * 16 + rbase + hh * 8;
            if (gm >= M) continue;
            #pragma unroll
            for (int nt = 0; nt < 8; nt++) {
                int gn = wn * 64 + nt * 8 + col2;
                float2 o;
                o.x = fmaxf(acc[mt][nt][hh * 2]     + bias[gn],     0.f);
                o.y = fmaxf(acc[mt][nt][hh * 2 + 1] + bias[gn + 1], 0.f);
                *(float2*)(out + (size_t)gm * HD + gn) = o;
            }
        }
    }
}

extern "C" void kernel_launch(void* const* d_in, const int* in_sizes, int n_in,
                              void* d_out, int out_size)
{
    const float* h       = (const float*)d_in[0];
    const float* norm    = (const float*)d_in[1];
    const float* basis_w = (const float*)d_in[2];
    const float* w_comp  = (const float*)d_in[3];
    const float* loop_w  = (const float*)d_in[4];
    const float* bias    = (const float*)d_in[5];
    const int*   src     = (const int*)d_in[6];
    const int*   dst     = (const int*)d_in[7];
    const int*   etype   = (const int*)d_in[8];
    float* out = (float*)d_out;

    int M = in_sizes[0] / HD;   // 50000
    int E = in_sizes[6];        // 800000

    cudaFuncSetAttribute(gemm2_k, cudaFuncAttributeMaxDynamicSharedMemorySize, SMEM_BYTES);

    prep_k<<<(NP * 32 + 255) / 256, 256>>>(h, basis_w, loop_w, M);
    hist_k<<<((E + 3) / 4 + 255) / 256, 256>>>(dst, E);
    scan_k<<<NBLK, 256>>>();
    bucket_k<<<((E + 3) / 4 + 255) / 256, 256>>>(w_comp, norm, src, dst, etype, E);
    accum_k<<<(NP * 32 + 255) / 256, 256>>>();
    gemm2_k<<<NP / 128, 256, SMEM_BYTES>>>(bias, out, M);
}